// round 5
// baseline (speedup 1.0000x reference)
#include <cuda_runtime.h>
#include <math.h>

#define Sd   2048
#define Hd   2048
#define NHd  16
#define Dd   128
#define Ed   8
#define IEd  1408
#define ISd  5632

// ---------------- static scratch (no allocations allowed) ----------------
__device__ float g_h1[Sd * Hd];
__device__ float g_q[Sd * Hd];
__device__ float g_k[Sd * Hd];
__device__ float g_v[Sd * Hd];
__device__ float g_scores[16 * 2048 * 2048];   // [NH, S, S]  (268 MB)
__device__ float g_attn[Sd * Hd];
__device__ float g_h2[Sd * Hd];
__device__ float g_w[Sd * Ed];
__device__ int   g_cnt[Ed];
__device__ int   g_idx[Ed * Sd];
__device__ float g_G[Sd * IEd];
__device__ float g_U[Sd * IEd];
__device__ float g_Y[Sd * Hd];
__device__ float g_SG[Sd * ISd];
__device__ float g_SU[Sd * ISd];
__device__ float g_sig[Sd];

// ---------------- generic fp32 SGEMM: 128x128 block, 8x8 microtile ----------------
// C[M,N] = A @ B (or A @ B^T when TB), optional bias[n], optional residual add,
// optional gathered A rows (a_rows/a_cnt), causal modes:
//   causal==1 : skip blocks fully above the diagonal (scores GEMM)
//   causal==2 : limit K loop to mBase+128 (PV GEMM; probs are 0 beyond)
template <bool TB>
__global__ __launch_bounds__(256, 2)
void sgemm_kernel(const float* __restrict__ A, const float* __restrict__ B,
                  float* __restrict__ C,
                  int M, int N, int K, int lda, int ldb, int ldc,
                  long long sAz, long long sBz, long long sCz,
                  const float* __restrict__ bias,
                  const float* __restrict__ residual, int ldr,
                  const int* __restrict__ a_rows, const int* __restrict__ a_cnt,
                  int causal)
{
    const int mBase = blockIdx.y * 128;
    const int nBase = blockIdx.x * 128;
    if (causal == 1 && nBase >= mBase + 128) return;      // fully masked block
    int count = M;
    if (a_cnt) { count = *a_cnt; if (count <= 0 || mBase >= count) return; }

    const int bz = blockIdx.z;
    A += bz * sAz;  B += bz * sBz;  C += bz * sCz;

    int kEnd = K;
    if (causal == 2) { int kl = mBase + 128; if (kl < kEnd) kEnd = kl; }

    __shared__ float As[8][128];
    __shared__ float Bs[8][128];

    const int tid = threadIdx.x;
    const int tx = tid & 15;
    const int ty = tid >> 4;

    // A tile loader: 128 rows x 8 k, one float4 per thread (along K), transposed into smem
    const int ar  = tid >> 1;
    const int ac4 = (tid & 1) << 2;
    int arowG = mBase + ar;
    if (a_rows) { int rr = arowG < count ? arowG : (count - 1); arowG = a_rows[rr]; }
    const float* Aptr = A + (long long)arowG * lda + ac4;

    // B tile loader
    const float* Bptr;
    int bn_ = 0, bk4 = 0, brow = 0, bcol = 0;
    if (TB) {                       // B is [N,K] row-major; need Bs[k][n]=B[n][k]
        bn_ = tid >> 1; bk4 = (tid & 1) << 2;
        Bptr = B + (long long)(nBase + bn_) * ldb + bk4;
    } else {                        // B is [K,N] row-major
        brow = tid >> 5; bcol = (tid & 31) << 2;
        Bptr = B + (long long)brow * ldb + nBase + bcol;
    }

    float acc[8][8];
#pragma unroll
    for (int i = 0; i < 8; i++)
#pragma unroll
        for (int j = 0; j < 8; j++) acc[i][j] = 0.f;

    for (int k0 = 0; k0 < kEnd; k0 += 8) {
        float4 av = *reinterpret_cast<const float4*>(Aptr + k0);
        float4 bv;
        if (TB) bv = *reinterpret_cast<const float4*>(Bptr + k0);
        else    bv = *reinterpret_cast<const float4*>(Bptr + (long long)k0 * ldb);

        __syncthreads();
        As[ac4 + 0][ar] = av.x; As[ac4 + 1][ar] = av.y;
        As[ac4 + 2][ar] = av.z; As[ac4 + 3][ar] = av.w;
        if (TB) {
            Bs[bk4 + 0][bn_] = bv.x; Bs[bk4 + 1][bn_] = bv.y;
            Bs[bk4 + 2][bn_] = bv.z; Bs[bk4 + 3][bn_] = bv.w;
        } else {
            *reinterpret_cast<float4*>(&Bs[brow][bcol]) = bv;
        }
        __syncthreads();

#pragma unroll
        for (int kk = 0; kk < 8; kk++) {
            float ra[8], rb[8];
#pragma unroll
            for (int i = 0; i < 4; i++) {
                ra[i]     = As[kk][ty * 4 + i];
                ra[i + 4] = As[kk][64 + ty * 4 + i];
            }
#pragma unroll
            for (int j = 0; j < 4; j++) {
                rb[j]     = Bs[kk][tx * 4 + j];
                rb[j + 4] = Bs[kk][64 + tx * 4 + j];
            }
#pragma unroll
            for (int i = 0; i < 8; i++)
#pragma unroll
                for (int j = 0; j < 8; j++)
                    acc[i][j] = fmaf(ra[i], rb[j], acc[i][j]);
        }
    }

#pragma unroll
    for (int i = 0; i < 8; i++) {
        int mi = (i < 4) ? (ty * 4 + i) : (64 + ty * 4 + i - 4);
        int gm = mBase + mi;
        if (gm >= count) continue;
#pragma unroll
        for (int j = 0; j < 8; j++) {
            int nj = (j < 4) ? (tx * 4 + j) : (64 + tx * 4 + j - 4);
            int gn = nBase + nj;
            float v = acc[i][j];
            if (bias)     v += bias[gn];
            if (residual) v += residual[(long long)gm * ldr + gn];
            C[(long long)gm * ldc + gn] = v;
        }
    }
}

// ---------------- elementwise / reduction kernels ----------------
__global__ void reset_cnt_kernel(int* cnt)
{
    if (threadIdx.x < Ed) cnt[threadIdx.x] = 0;
}

__global__ void rmsnorm_kernel(const float* __restrict__ x, const float* __restrict__ w,
                               float* __restrict__ y)
{
    int s = blockIdx.x, tid = threadIdx.x;
    __shared__ float red[256];
    __shared__ float srs;
    const float* xr = x + (long long)s * Hd;
    float sum = 0.f;
    for (int h = tid; h < Hd; h += 256) { float v = xr[h]; sum += v * v; }
    red[tid] = sum; __syncthreads();
    for (int st = 128; st > 0; st >>= 1) {
        if (tid < st) red[tid] += red[tid + st];
        __syncthreads();
    }
    if (tid == 0) srs = rsqrtf(red[0] / (float)Hd + 1e-6f);
    __syncthreads();
    float rs = srs;
    float* yr = y + (long long)s * Hd;
    for (int h = tid; h < Hd; h += 256) yr[h] = w[h] * xr[h] * rs;
}

__global__ void rope_kernel(float* __restrict__ q, float* __restrict__ k)
{
    int i = blockIdx.x * 256 + threadIdx.x;           // S*NH*64 total
    int hi = i & 63;
    int h  = (i >> 6) & 15;
    int s  = i >> 10;
    float inv = powf(1000000.0f, -(float)hi / 64.0f);
    float ang = (float)s * inv;
    float sv, cv; sincosf(ang, &sv, &cv);
    long long base = (long long)s * Hd + h * Dd + hi;
    float q1 = q[base], q2 = q[base + 64];
    q[base]      = q1 * cv - q2 * sv;
    q[base + 64] = q2 * cv + q1 * sv;
    float k1 = k[base], k2 = k[base + 64];
    k[base]      = k1 * cv - k2 * sv;
    k[base + 64] = k2 * cv + k1 * sv;
}

__global__ void softmax_kernel(float* __restrict__ scores)
{
    int s = blockIdx.x, h = blockIdx.y, tid = threadIdx.x;
    float* row = scores + ((long long)h * Sd + s) * Sd;
    const float scale = 0.08838834764831845f;         // 1/sqrt(128)
    float r[8];
    float mx = -3.4e38f;
#pragma unroll
    for (int t = 0; t < 8; t++) {
        int kk = t * 256 + tid;
        float v = (kk <= s) ? row[kk] * scale : -3.4e38f;
        r[t] = v; mx = fmaxf(mx, v);
    }
    __shared__ float red[256];
    red[tid] = mx; __syncthreads();
    for (int st = 128; st > 0; st >>= 1) {
        if (tid < st) red[tid] = fmaxf(red[tid], red[tid + st]);
        __syncthreads();
    }
    mx = red[0]; __syncthreads();
    float sum = 0.f;
#pragma unroll
    for (int t = 0; t < 8; t++) {
        int kk = t * 256 + tid;
        if (kk <= s) { r[t] = expf(r[t] - mx); sum += r[t]; }
        else r[t] = 0.f;
    }
    red[tid] = sum; __syncthreads();
    for (int st = 128; st > 0; st >>= 1) {
        if (tid < st) red[tid] += red[tid + st];
        __syncthreads();
    }
    float inv = 1.0f / red[0];
#pragma unroll
    for (int t = 0; t < 8; t++) row[t * 256 + tid] = r[t] * inv;
}

__global__ void router_kernel(const float* __restrict__ h2, const float* __restrict__ gate_w,
                              float* __restrict__ logits_out, float* __restrict__ w_out,
                              int* __restrict__ cnt, int* __restrict__ idx)
{
    int s = blockIdx.x, tid = threadIdx.x;
    __shared__ float red[256][8];
    float loc[8];
#pragma unroll
    for (int e = 0; e < 8; e++) loc[e] = 0.f;
    const float* hr = h2 + (long long)s * Hd;
    for (int h = tid; h < Hd; h += 256) {
        float hv = hr[h];
#pragma unroll
        for (int e = 0; e < 8; e++) loc[e] += hv * gate_w[h * 8 + e];
    }
#pragma unroll
    for (int e = 0; e < 8; e++) red[tid][e] = loc[e];
    __syncthreads();
    for (int st = 128; st > 0; st >>= 1) {
        if (tid < st) {
#pragma unroll
            for (int e = 0; e < 8; e++) red[tid][e] += red[tid + st][e];
        }
        __syncthreads();
    }
    if (tid == 0) {
        float l[8], p[8], w[8];
        float mx = -3.4e38f;
#pragma unroll
        for (int e = 0; e < 8; e++) { l[e] = red[0][e]; logits_out[s * 8 + e] = l[e]; mx = fmaxf(mx, l[e]); }
        float sum = 0.f;
#pragma unroll
        for (int e = 0; e < 8; e++) { p[e] = expf(l[e] - mx); sum += p[e]; }
#pragma unroll
        for (int e = 0; e < 8; e++) { p[e] /= sum; w[e] = 0.f; }
        bool used[8] = {false, false, false, false, false, false, false, false};
        for (int t = 0; t < 4; t++) {
            int best = -1; float bv = -1.f;
            for (int e = 0; e < 8; e++)
                if (!used[e] && p[e] > bv) { bv = p[e]; best = e; }
            used[best] = true; w[best] = bv;
            int pos = atomicAdd(&cnt[best], 1);
            idx[best * Sd + pos] = s;
        }
#pragma unroll
        for (int e = 0; e < 8; e++) w_out[s * 8 + e] = w[e];
    }
}

__global__ void silu_mul_kernel(float* __restrict__ G, const float* __restrict__ U,
                                const int* __restrict__ cnt, int ncols)
{
    long long i = (long long)blockIdx.x * 256 + threadIdx.x;
    int r = (int)(i / ncols);
    if (cnt && r >= *cnt) return;
    float g = G[i], u = U[i];
    G[i] = (g / (1.f + expf(-g))) * u;
}

__global__ void scatter_kernel(float* __restrict__ out, const float* __restrict__ Y,
                               const float* __restrict__ w, const int* __restrict__ idx,
                               const int* __restrict__ cnt, int e)
{
    int i = blockIdx.x * 256 + threadIdx.x;
    int r = i >> 11, c = i & 2047;
    if (r >= cnt[e]) return;
    int s = idx[e * Sd + r];
    out[(long long)s * Hd + c] += w[s * Ed + e] * Y[i];
}

__global__ void sgate_kernel(const float* __restrict__ h2, const float* __restrict__ sgate,
                             float* __restrict__ sig)
{
    int s = blockIdx.x, tid = threadIdx.x;
    __shared__ float red[256];
    const float* hr = h2 + (long long)s * Hd;
    float sum = 0.f;
    for (int h = tid; h < Hd; h += 256) sum += hr[h] * sgate[h];
    red[tid] = sum; __syncthreads();
    for (int st = 128; st > 0; st >>= 1) {
        if (tid < st) red[tid] += red[tid + st];
        __syncthreads();
    }
    if (tid == 0) sig[s] = 1.f / (1.f + expf(-red[0]));
}

__global__ void add_shared_kernel(float* __restrict__ out, const float* __restrict__ Y,
                                  const float* __restrict__ sig)
{
    int i = blockIdx.x * 256 + threadIdx.x;
    int r = i >> 11;
    out[i] += sig[r] * Y[i];
}

// ---------------- host-side GEMM dispatch ----------------
static inline void gemm(bool tb, const float* A, const float* B, float* C,
                        int M, int N, int K, int lda, int ldb, int ldc,
                        long long sA = 0, long long sB = 0, long long sC = 0, int nz = 1,
                        const float* bias = nullptr,
                        const float* residual = nullptr, int ldr = 0,
                        const int* arows = nullptr, const int* acnt = nullptr,
                        int causal = 0)
{
    dim3 grid(N / 128, (M + 127) / 128, nz);
    if (tb)
        sgemm_kernel<true><<<grid, 256>>>(A, B, C, M, N, K, lda, ldb, ldc,
                                          sA, sB, sC, bias, residual, ldr, arows, acnt, causal);
    else
        sgemm_kernel<false><<<grid, 256>>>(A, B, C, M, N, K, lda, ldb, ldc,
                                           sA, sB, sC, bias, residual, ldr, arows, acnt, causal);
}

extern "C" void kernel_launch(void* const* d_in, const int* in_sizes, int n_in,
                              void* d_out, int out_size)
{
    const float* x     = (const float*)d_in[0];
    const float* ln1   = (const float*)d_in[1];
    const float* ln2   = (const float*)d_in[2];
    const float* wq    = (const float*)d_in[3];
    const float* bq    = (const float*)d_in[4];
    const float* wk    = (const float*)d_in[5];
    const float* bk    = (const float*)d_in[6];
    const float* wv    = (const float*)d_in[7];
    const float* bv    = (const float*)d_in[8];
    const float* wo    = (const float*)d_in[9];
    const float* gate  = (const float*)d_in[10];
    const float* eg    = (const float*)d_in[11];
    const float* eu    = (const float*)d_in[12];
    const float* ed    = (const float*)d_in[13];
    const float* sg    = (const float*)d_in[14];
    const float* su    = (const float*)d_in[15];
    const float* sd    = (const float*)d_in[16];
    const float* sgate = (const float*)d_in[17];

    float* out        = (float*)d_out;
    float* out_x      = out;                          // [S, H]
    float* out_logits = out + (long long)Sd * Hd;     // [S, E]

    float *h1, *q, *k, *v, *scores, *attn, *h2, *w, *G, *U, *Y, *SG, *SU, *sig;
    int *cnt, *idx;
    cudaGetSymbolAddress((void**)&h1,     g_h1);
    cudaGetSymbolAddress((void**)&q,      g_q);
    cudaGetSymbolAddress((void**)&k,      g_k);
    cudaGetSymbolAddress((void**)&v,      g_v);
    cudaGetSymbolAddress((void**)&scores, g_scores);
    cudaGetSymbolAddress((void**)&attn,   g_attn);
    cudaGetSymbolAddress((void**)&h2,     g_h2);
    cudaGetSymbolAddress((void**)&w,      g_w);
    cudaGetSymbolAddress((void**)&G,      g_G);
    cudaGetSymbolAddress((void**)&U,      g_U);
    cudaGetSymbolAddress((void**)&Y,      g_Y);
    cudaGetSymbolAddress((void**)&SG,     g_SG);
    cudaGetSymbolAddress((void**)&SU,     g_SU);
    cudaGetSymbolAddress((void**)&sig,    g_sig);
    cudaGetSymbolAddress((void**)&cnt,    g_cnt);
    cudaGetSymbolAddress((void**)&idx,    g_idx);

    // 0. reset expert counters
    reset_cnt_kernel<<<1, 32>>>(cnt);

    // 1. rmsnorm -> h1
    rmsnorm_kernel<<<Sd, 256>>>(x, ln1, h1);

    // 2. QKV projections (+bias)
    gemm(false, h1, wq, q, Sd, Hd, Hd, Hd, Hd, Hd, 0, 0, 0, 1, bq);
    gemm(false, h1, wk, k, Sd, Hd, Hd, Hd, Hd, Hd, 0, 0, 0, 1, bk);
    gemm(false, h1, wv, v, Sd, Hd, Hd, Hd, Hd, Hd, 0, 0, 0, 1, bv);

    // 3. RoPE (in place on q, k)
    rope_kernel<<<(Sd * NHd * 64) / 256, 256>>>(q, k);

    // 4. scores[h] = q_h @ k_h^T (batched over heads, causal block-skip)
    gemm(true, q, k, scores, Sd, Sd, Dd, Hd, Hd, Sd,
         128, 128, (long long)Sd * Sd, NHd, nullptr, nullptr, 0, nullptr, nullptr, 1);

    // 5. causal softmax (writes zeros above the diagonal)
    softmax_kernel<<<dim3(Sd, NHd), 256>>>(scores);

    // 6. attn[h] = probs_h @ v_h (batched, K-loop causally capped)
    gemm(false, scores, v, attn, Sd, Dd, Sd, Sd, Hd, Hd,
         (long long)Sd * Sd, 128, 128, NHd, nullptr, nullptr, 0, nullptr, nullptr, 2);

    // 7. x2 = x + attn @ wo  -> directly into output buffer
    gemm(false, attn, wo, out_x, Sd, Hd, Hd, Hd, Hd, Hd, 0, 0, 0, 1, nullptr, x, Hd);

    // 8. rmsnorm -> h2
    rmsnorm_kernel<<<Sd, 256>>>(out_x, ln2, h2);

    // 9. router: logits, softmax top-4 weights, per-expert token lists
    router_kernel<<<Sd, 256>>>(h2, gate, out_logits, w, cnt, idx);

    // 10. routed MoE: per-expert gathered GEMMs + race-free scatter-add
    for (int e = 0; e < Ed; e++) {
        const float* ege = eg + (long long)e * Hd * IEd;
        const float* eue = eu + (long long)e * Hd * IEd;
        const float* ede = ed + (long long)e * IEd * Hd;
        gemm(false, h2, ege, G, Sd, IEd, Hd, Hd, IEd, IEd, 0, 0, 0, 1,
             nullptr, nullptr, 0, idx + e * Sd, cnt + e, 0);
        gemm(false, h2, eue, U, Sd, IEd, Hd, Hd, IEd, IEd, 0, 0, 0, 1,
             nullptr, nullptr, 0, idx + e * Sd, cnt + e, 0);
        silu_mul_kernel<<<(Sd * IEd) / 256, 256>>>(G, U, cnt + e, IEd);
        gemm(false, G, ede, Y, Sd, Hd, IEd, IEd, Hd, Hd, 0, 0, 0, 1,
             nullptr, nullptr, 0, nullptr, cnt + e, 0);
        scatter_kernel<<<(Sd * Hd) / 256, 256>>>(out_x, Y, w, idx, cnt, e);
    }

    // 11. shared expert
    gemm(false, h2, sg, SG, Sd, ISd, Hd, Hd, ISd, ISd);
    gemm(false, h2, su, SU, Sd, ISd, Hd, Hd, ISd, ISd);
    silu_mul_kernel<<<(int)(((long long)Sd * ISd) / 256), 256>>>(SG, SU, nullptr, ISd);
    gemm(false, SG, sd, Y, Sd, Hd, ISd, ISd, Hd, Hd);
    sgate_kernel<<<Sd, 256>>>(h2, sgate, sig);
    add_shared_kernel<<<(Sd * Hd) / 256, 256>>>(out_x, Y, sig);

    (void)in_sizes; (void)n_in; (void)out_size;
}

// round 7
// speedup vs baseline: 3.1905x; 3.1905x over previous
#include <cuda_runtime.h>
#include <math.h>
#include <stdint.h>

#define Sd   2048
#define Hd   2048
#define NHd  16
#define Dd   128
#define Ed   8
#define IEd  1408
#define ISd  5632

// ---------------- static scratch (no allocations allowed) ----------------
__device__ float g_h1[Sd * Hd];
__device__ float g_q[Sd * Hd];
__device__ float g_k[Sd * Hd];
__device__ float g_v[Sd * Hd];
__device__ float g_scores[16 * 2048 * 2048];   // [NH, S, S]
__device__ float g_attn[Sd * Hd];
__device__ float g_h2[Sd * Hd];
__device__ float g_w[Sd * Ed];
__device__ int   g_cnt[Ed];
__device__ int   g_idx[Ed * Sd];
__device__ float g_G[Sd * IEd];
__device__ float g_U[Sd * IEd];
__device__ float g_Y[Sd * Hd];
__device__ float g_SG[Sd * ISd];
__device__ float g_SU[Sd * ISd];
__device__ float g_sig[Sd];

__device__ __forceinline__ uint32_t cvt_tf32(float f) {
    uint32_t r;
    asm("cvt.rna.tf32.f32 %0, %1;" : "=r"(r) : "f"(f));
    return r;
}
__device__ __forceinline__ uint4 cvt4(float4 v) {
    return make_uint4(cvt_tf32(v.x), cvt_tf32(v.y), cvt_tf32(v.z), cvt_tf32(v.w));
}

__device__ __forceinline__ void mma_tf32(float* c, const uint32_t* a, const uint32_t* b) {
    asm volatile(
        "mma.sync.aligned.m16n8k8.row.col.f32.tf32.tf32.f32 "
        "{%0,%1,%2,%3}, {%4,%5,%6,%7}, {%8,%9}, {%0,%1,%2,%3};\n"
        : "+f"(c[0]), "+f"(c[1]), "+f"(c[2]), "+f"(c[3])
        : "r"(a[0]), "r"(a[1]), "r"(a[2]), "r"(a[3]), "r"(b[0]), "r"(b[1]));
}

// ---------------- tf32 mma.sync GEMM: 128x128 tile, BK=32 ----------------
// C[M,N] = A @ B.  A is [M,K] row-major (optionally row-gathered).
// BNK==true : B given as [N,K] row-major (scores GEMM, B^T semantics).
// BNK==false: B given as [K,N] row-major (weight matrices).
// causal==1: skip blocks fully above the diagonal.  causal==2: cap K at mBase+128.
template <bool BNK>
__global__ __launch_bounds__(256, 2)
void mgemm_kernel(const float* __restrict__ A, const float* __restrict__ B,
                  float* __restrict__ C,
                  int M, int N, int K, int lda, int ldb, int ldc,
                  long long sAz, long long sBz, long long sCz,
                  const float* __restrict__ bias,
                  const float* __restrict__ residual, int ldr,
                  const int* __restrict__ a_rows, const int* __restrict__ a_cnt,
                  int causal)
{
    const int mBase = blockIdx.y * 128;
    const int nBase = blockIdx.x * 128;
    if (causal == 1 && nBase >= mBase + 128) return;
    int count = M;
    if (a_cnt) { count = *a_cnt; if (count <= 0 || mBase >= count) return; }

    A += (long long)blockIdx.z * sAz;
    B += (long long)blockIdx.z * sBz;
    C += (long long)blockIdx.z * sCz;

    int kEnd = K;
    if (causal == 2) { int kl = mBase + 128; if (kl < kEnd) kEnd = kl; }
    const int nCh = kEnd >> 5;

    __shared__ float As[128 * 36];                     // [m][k], stride 36 -> frag reads conflict-free
    __shared__ float Bs[BNK ? 128 * 36 : 32 * 136];    // [n][k] s36  |  [k][n] s136, both conflict-free

    const int tid  = threadIdx.x;
    const int lane = tid & 31;
    const int wid  = tid >> 5;
    const int wm   = (wid >> 2) * 64;
    const int wn   = (wid & 3) * 32;
    const int gr   = lane >> 2;      // groupID
    const int tg   = lane & 3;       // threadID_in_group

    // ---- loader mapping ----
    const int ar0 = tid >> 3;                 // 0..31
    const int ac  = (tid & 7) * 4;            // 0..28
    const float* aPtr[4];
#pragma unroll
    for (int j = 0; j < 4; j++) {
        int r = mBase + ar0 + 32 * j;
        if (a_rows) r = a_rows[r < count ? r : count - 1];
        aPtr[j] = A + (long long)r * lda + ac;
    }
    const float* bPtr[4];
    int br0 = 0, bc = 0;
    if (BNK) {
#pragma unroll
        for (int j = 0; j < 4; j++)
            bPtr[j] = B + (long long)(nBase + ar0 + 32 * j) * ldb + ac;
    } else {
        br0 = tid >> 5;                       // 0..7
        bc  = (tid & 31) * 4;                 // 0..124
#pragma unroll
        for (int j = 0; j < 4; j++)
            bPtr[j] = B + (long long)(br0 + 8 * j) * ldb + nBase + bc;
    }

    float acc[4][4][4];
#pragma unroll
    for (int mi = 0; mi < 4; mi++)
#pragma unroll
        for (int ni = 0; ni < 4; ni++)
#pragma unroll
            for (int e = 0; e < 4; e++) acc[mi][ni][e] = 0.f;

    for (int c = 0; c < nCh; c++) {
        const int k0 = c << 5;
        if (c) __syncthreads();

#pragma unroll
        for (int j = 0; j < 4; j++) {
            float4 v = *(const float4*)(aPtr[j] + k0);
            *(uint4*)&As[(ar0 + 32 * j) * 36 + ac] = cvt4(v);
        }
        if (BNK) {
#pragma unroll
            for (int j = 0; j < 4; j++) {
                float4 v = *(const float4*)(bPtr[j] + k0);
                *(uint4*)&Bs[(ar0 + 32 * j) * 36 + ac] = cvt4(v);
            }
        } else {
#pragma unroll
            for (int j = 0; j < 4; j++) {
                float4 v = *(const float4*)(bPtr[j] + (long long)k0 * ldb);
                *(uint4*)&Bs[(br0 + 8 * j) * 136 + bc] = cvt4(v);
            }
        }
        __syncthreads();

#pragma unroll
        for (int kk = 0; kk < 4; kk++) {
            const int ko = kk * 8;
            uint32_t af[4][4];
#pragma unroll
            for (int mi = 0; mi < 4; mi++) {
                const float* p = &As[(wm + mi * 16 + gr) * 36 + ko + tg];
                af[mi][0] = __float_as_uint(p[0]);
                af[mi][1] = __float_as_uint(p[8 * 36]);
                af[mi][2] = __float_as_uint(p[4]);
                af[mi][3] = __float_as_uint(p[8 * 36 + 4]);
            }
            uint32_t bf[4][2];
#pragma unroll
            for (int ni = 0; ni < 4; ni++) {
                if (BNK) {
                    const float* p = &Bs[(wn + ni * 8 + gr) * 36 + ko + tg];
                    bf[ni][0] = __float_as_uint(p[0]);
                    bf[ni][1] = __float_as_uint(p[4]);
                } else {
                    const float* p = &Bs[(ko + tg) * 136 + wn + ni * 8 + gr];
                    bf[ni][0] = __float_as_uint(p[0]);
                    bf[ni][1] = __float_as_uint(p[4 * 136]);
                }
            }
#pragma unroll
            for (int mi = 0; mi < 4; mi++)
#pragma unroll
                for (int ni = 0; ni < 4; ni++)
                    mma_tf32(acc[mi][ni], af[mi], bf[ni]);
        }
    }

    // ---- epilogue ----
#pragma unroll
    for (int mi = 0; mi < 4; mi++) {
        const int gm0 = mBase + wm + mi * 16 + gr;
        const int gm1 = gm0 + 8;
        const bool ok0 = gm0 < count;
        const bool ok1 = gm1 < count;
#pragma unroll
        for (int ni = 0; ni < 4; ni++) {
            const int gn = nBase + wn + ni * 8 + tg * 2;
            float2 v0 = make_float2(acc[mi][ni][0], acc[mi][ni][1]);
            float2 v1 = make_float2(acc[mi][ni][2], acc[mi][ni][3]);
            if (bias) {
                float2 b = *(const float2*)(bias + gn);
                v0.x += b.x; v0.y += b.y; v1.x += b.x; v1.y += b.y;
            }
            if (ok0) {
                if (residual) {
                    float2 r = *(const float2*)(residual + (long long)gm0 * ldr + gn);
                    v0.x += r.x; v0.y += r.y;
                }
                *(float2*)(C + (long long)gm0 * ldc + gn) = v0;
            }
            if (ok1) {
                if (residual) {
                    float2 r = *(const float2*)(residual + (long long)gm1 * ldr + gn);
                    v1.x += r.x; v1.y += r.y;
                }
                *(float2*)(C + (long long)gm1 * ldc + gn) = v1;
            }
        }
    }
}

// ---------------- elementwise / reduction kernels ----------------
__global__ void reset_cnt_kernel(int* cnt)
{
    if (threadIdx.x < Ed) cnt[threadIdx.x] = 0;
}

__global__ void rmsnorm_kernel(const float* __restrict__ x, const float* __restrict__ w,
                               float* __restrict__ y)
{
    int s = blockIdx.x, tid = threadIdx.x;
    __shared__ float red[256];
    __shared__ float srs;
    const float* xr = x + (long long)s * Hd;
    float sum = 0.f;
    for (int h = tid; h < Hd; h += 256) { float v = xr[h]; sum += v * v; }
    red[tid] = sum; __syncthreads();
    for (int st = 128; st > 0; st >>= 1) {
        if (tid < st) red[tid] += red[tid + st];
        __syncthreads();
    }
    if (tid == 0) srs = rsqrtf(red[0] / (float)Hd + 1e-6f);
    __syncthreads();
    float rs = srs;
    float* yr = y + (long long)s * Hd;
    for (int h = tid; h < Hd; h += 256) yr[h] = w[h] * xr[h] * rs;
}

__global__ void rope_kernel(float* __restrict__ q, float* __restrict__ k)
{
    int i = blockIdx.x * 256 + threadIdx.x;
    int hi = i & 63;
    int h  = (i >> 6) & 15;
    int s  = i >> 10;
    float inv = powf(1000000.0f, -(float)hi / 64.0f);
    float ang = (float)s * inv;
    float sv, cv; sincosf(ang, &sv, &cv);
    long long base = (long long)s * Hd + h * Dd + hi;
    float q1 = q[base], q2 = q[base + 64];
    q[base]      = q1 * cv - q2 * sv;
    q[base + 64] = q2 * cv + q1 * sv;
    float k1 = k[base], k2 = k[base + 64];
    k[base]      = k1 * cv - k2 * sv;
    k[base + 64] = k2 * cv + k1 * sv;
}

__global__ void softmax_kernel(float* __restrict__ scores)
{
    int s = blockIdx.x, h = blockIdx.y, tid = threadIdx.x;
    float* row = scores + ((long long)h * Sd + s) * Sd;
    const float scale = 0.08838834764831845f;
    int limit = ((s >> 7) + 1) << 7;           // only [0, limit) is read by PV GEMM
    float r[8];
    float mx = -3.4e38f;
#pragma unroll
    for (int t = 0; t < 8; t++) {
        int kk = t * 256 + tid;
        float v = -3.4e38f;
        if (kk <= s) v = row[kk] * scale;
        r[t] = v; mx = fmaxf(mx, v);
    }
    __shared__ float red[256];
    red[tid] = mx; __syncthreads();
    for (int st = 128; st > 0; st >>= 1) {
        if (tid < st) red[tid] = fmaxf(red[tid], red[tid + st]);
        __syncthreads();
    }
    mx = red[0]; __syncthreads();
    float sum = 0.f;
#pragma unroll
    for (int t = 0; t < 8; t++) {
        int kk = t * 256 + tid;
        if (kk <= s) { r[t] = expf(r[t] - mx); sum += r[t]; }
        else r[t] = 0.f;
    }
    red[tid] = sum; __syncthreads();
    for (int st = 128; st > 0; st >>= 1) {
        if (tid < st) red[tid] += red[tid + st];
        __syncthreads();
    }
    float inv = 1.0f / red[0];
#pragma unroll
    for (int t = 0; t < 8; t++) {
        int kk = t * 256 + tid;
        if (kk < limit) row[kk] = r[t] * inv;
    }
}

__global__ void router_kernel(const float* __restrict__ h2, const float* __restrict__ gate_w,
                              float* __restrict__ logits_out, float* __restrict__ w_out,
                              int* __restrict__ cnt, int* __restrict__ idx)
{
    int s = blockIdx.x, tid = threadIdx.x;
    __shared__ float red[256][8];
    float loc[8];
#pragma unroll
    for (int e = 0; e < 8; e++) loc[e] = 0.f;
    const float* hr = h2 + (long long)s * Hd;
    for (int h = tid; h < Hd; h += 256) {
        float hv = hr[h];
#pragma unroll
        for (int e = 0; e < 8; e++) loc[e] += hv * gate_w[h * 8 + e];
    }
#pragma unroll
    for (int e = 0; e < 8; e++) red[tid][e] = loc[e];
    __syncthreads();
    for (int st = 128; st > 0; st >>= 1) {
        if (tid < st) {
#pragma unroll
            for (int e = 0; e < 8; e++) red[tid][e] += red[tid + st][e];
        }
        __syncthreads();
    }
    if (tid == 0) {
        float l[8], p[8], w[8];
        float mx = -3.4e38f;
#pragma unroll
        for (int e = 0; e < 8; e++) { l[e] = red[0][e]; logits_out[s * 8 + e] = l[e]; mx = fmaxf(mx, l[e]); }
        float sum = 0.f;
#pragma unroll
        for (int e = 0; e < 8; e++) { p[e] = expf(l[e] - mx); sum += p[e]; }
#pragma unroll
        for (int e = 0; e < 8; e++) { p[e] /= sum; w[e] = 0.f; }
        bool used[8] = {false, false, false, false, false, false, false, false};
        for (int t = 0; t < 4; t++) {
            int best = -1; float bv = -1.f;
            for (int e = 0; e < 8; e++)
                if (!used[e] && p[e] > bv) { bv = p[e]; best = e; }
            used[best] = true; w[best] = bv;
            int pos = atomicAdd(&cnt[best], 1);
            idx[best * Sd + pos] = s;
        }
#pragma unroll
        for (int e = 0; e < 8; e++) w_out[s * 8 + e] = w[e];
    }
}

__global__ void silu_mul_kernel(float* __restrict__ G, const float* __restrict__ U,
                                const int* __restrict__ cnt, int ncols)
{
    long long i = (long long)blockIdx.x * 256 + threadIdx.x;
    int r = (int)(i / ncols);
    if (cnt && r >= *cnt) return;
    float g = G[i], u = U[i];
    G[i] = (g / (1.f + expf(-g))) * u;
}

__global__ void scatter_kernel(float* __restrict__ out, const float* __restrict__ Y,
                               const float* __restrict__ w, const int* __restrict__ idx,
                               const int* __restrict__ cnt, int e)
{
    int i = blockIdx.x * 256 + threadIdx.x;
    int r = i >> 11, c = i & 2047;
    if (r >= cnt[e]) return;
    int s = idx[e * Sd + r];
    out[(long long)s * Hd + c] += w[s * Ed + e] * Y[i];
}

__global__ void sgate_kernel(const float* __restrict__ h2, const float* __restrict__ sgate,
                             float* __restrict__ sig)
{
    int s = blockIdx.x, tid = threadIdx.x;
    __shared__ float red[256];
    const float* hr = h2 + (long long)s * Hd;
    float sum = 0.f;
    for (int h = tid; h < Hd; h += 256) sum += hr[h] * sgate[h];
    red[tid] = sum; __syncthreads();
    for (int st = 128; st > 0; st >>= 1) {
        if (tid < st) red[tid] += red[tid + st];
        __syncthreads();
    }
    if (tid == 0) sig[s] = 1.f / (1.f + expf(-red[0]));
}

__global__ void add_shared_kernel(float* __restrict__ out, const float* __restrict__ Y,
                                  const float* __restrict__ sig)
{
    int i = blockIdx.x * 256 + threadIdx.x;
    int r = i >> 11;
    out[i] += sig[r] * Y[i];
}

// ---------------- host-side GEMM dispatch ----------------
static inline void tgemm(bool bnk, const float* A, const float* B, float* C,
                         int M, int N, int K, int lda, int ldb, int ldc,
                         long long sA = 0, long long sB = 0, long long sC = 0, int nz = 1,
                         const float* bias = nullptr,
                         const float* residual = nullptr, int ldr = 0,
                         const int* arows = nullptr, const int* acnt = nullptr,
                         int causal = 0)
{
    dim3 grid(N / 128, (M + 127) / 128, nz);
    if (bnk)
        mgemm_kernel<true><<<grid, 256>>>(A, B, C, M, N, K, lda, ldb, ldc,
                                          sA, sB, sC, bias, residual, ldr, arows, acnt, causal);
    else
        mgemm_kernel<false><<<grid, 256>>>(A, B, C, M, N, K, lda, ldb, ldc,
                                           sA, sB, sC, bias, residual, ldr, arows, acnt, causal);
}

extern "C" void kernel_launch(void* const* d_in, const int* in_sizes, int n_in,
                              void* d_out, int out_size)
{
    const float* x     = (const float*)d_in[0];
    const float* ln1   = (const float*)d_in[1];
    const float* ln2   = (const float*)d_in[2];
    const float* wq    = (const float*)d_in[3];
    const float* bq    = (const float*)d_in[4];
    const float* wk    = (const float*)d_in[5];
    const float* bk    = (const float*)d_in[6];
    const float* wv    = (const float*)d_in[7];
    const float* bv    = (const float*)d_in[8];
    const float* wo    = (const float*)d_in[9];
    const float* gate  = (const float*)d_in[10];
    const float* eg    = (const float*)d_in[11];
    const float* eu    = (const float*)d_in[12];
    const float* ed    = (const float*)d_in[13];
    const float* sg    = (const float*)d_in[14];
    const float* su    = (const float*)d_in[15];
    const float* sd    = (const float*)d_in[16];
    const float* sgate = (const float*)d_in[17];

    float* out        = (float*)d_out;
    float* out_x      = out;                          // [S, H]
    float* out_logits = out + (long long)Sd * Hd;     // [S, E]

    float *h1, *q, *k, *v, *scores, *attn, *h2, *w, *G, *U, *Y, *SG, *SU, *sig;
    int *cnt, *idx;
    cudaGetSymbolAddress((void**)&h1,     g_h1);
    cudaGetSymbolAddress((void**)&q,      g_q);
    cudaGetSymbolAddress((void**)&k,      g_k);
    cudaGetSymbolAddress((void**)&v,      g_v);
    cudaGetSymbolAddress((void**)&scores, g_scores);
    cudaGetSymbolAddress((void**)&attn,   g_attn);
    cudaGetSymbolAddress((void**)&h2,     g_h2);
    cudaGetSymbolAddress((void**)&w,      g_w);
    cudaGetSymbolAddress((void**)&G,      g_G);
    cudaGetSymbolAddress((void**)&U,      g_U);
    cudaGetSymbolAddress((void**)&Y,      g_Y);
    cudaGetSymbolAddress((void**)&SG,     g_SG);
    cudaGetSymbolAddress((void**)&SU,     g_SU);
    cudaGetSymbolAddress((void**)&sig,    g_sig);
    cudaGetSymbolAddress((void**)&cnt,    g_cnt);
    cudaGetSymbolAddress((void**)&idx,    g_idx);

    // 0. reset expert counters
    reset_cnt_kernel<<<1, 32>>>(cnt);

    // 1. rmsnorm -> h1
    rmsnorm_kernel<<<Sd, 256>>>(x, ln1, h1);

    // 2. QKV projections (+bias)   [B is [K,N] -> BNK=false]
    tgemm(false, h1, wq, q, Sd, Hd, Hd, Hd, Hd, Hd, 0, 0, 0, 1, bq);
    tgemm(false, h1, wk, k, Sd, Hd, Hd, Hd, Hd, Hd, 0, 0, 0, 1, bk);
    tgemm(false, h1, wv, v, Sd, Hd, Hd, Hd, Hd, Hd, 0, 0, 0, 1, bv);

    // 3. RoPE (in place)
    rope_kernel<<<(Sd * NHd * 64) / 256, 256>>>(q, k);

    // 4. scores[h] = q_h @ k_h^T   [B is [N,K] -> BNK=true, causal block-skip]
    tgemm(true, q, k, scores, Sd, Sd, Dd, Hd, Hd, Sd,
          128, 128, (long long)Sd * Sd, NHd, nullptr, nullptr, 0, nullptr, nullptr, 1);

    // 5. causal softmax
    softmax_kernel<<<dim3(Sd, NHd), 256>>>(scores);

    // 6. attn[h] = probs_h @ v_h   [B is [K,N] -> BNK=false, K capped causally]
    tgemm(false, scores, v, attn, Sd, Dd, Sd, Sd, Hd, Hd,
          (long long)Sd * Sd, 128, 128, NHd, nullptr, nullptr, 0, nullptr, nullptr, 2);

    // 7. x2 = x + attn @ wo -> output buffer
    tgemm(false, attn, wo, out_x, Sd, Hd, Hd, Hd, Hd, Hd, 0, 0, 0, 1, nullptr, x, Hd);

    // 8. rmsnorm -> h2
    rmsnorm_kernel<<<Sd, 256>>>(out_x, ln2, h2);

    // 9. router
    router_kernel<<<Sd, 256>>>(h2, gate, out_logits, w, cnt, idx);

    // 10. routed MoE
    for (int e = 0; e < Ed; e++) {
        const float* ege = eg + (long long)e * Hd * IEd;
        const float* eue = eu + (long long)e * Hd * IEd;
        const float* ede = ed + (long long)e * IEd * Hd;
        tgemm(false, h2, ege, G, Sd, IEd, Hd, Hd, IEd, IEd, 0, 0, 0, 1,
              nullptr, nullptr, 0, idx + e * Sd, cnt + e, 0);
        tgemm(false, h2, eue, U, Sd, IEd, Hd, Hd, IEd, IEd, 0, 0, 0, 1,
              nullptr, nullptr, 0, idx + e * Sd, cnt + e, 0);
        silu_mul_kernel<<<(Sd * IEd) / 256, 256>>>(G, U, cnt + e, IEd);
        tgemm(false, G, ede, Y, Sd, Hd, IEd, IEd, Hd, Hd, 0, 0, 0, 1,
              nullptr, nullptr, 0, nullptr, cnt + e, 0);
        scatter_kernel<<<(Sd * Hd) / 256, 256>>>(out_x, Y, w, idx, cnt, e);
    }

    // 11. shared expert
    tgemm(false, h2, sg, SG, Sd, ISd, Hd, Hd, ISd, ISd);
    tgemm(false, h2, su, SU, Sd, ISd, Hd, Hd, ISd, ISd);
    silu_mul_kernel<<<(int)(((long long)Sd * ISd) / 256), 256>>>(SG, SU, nullptr, ISd);
    tgemm(false, SG, sd, Y, Sd, Hd, ISd, ISd, Hd, Hd);
    sgate_kernel<<<Sd, 256>>>(h2, sgate, sig);
    add_shared_kernel<<<(Sd * Hd) / 256, 256>>>(out_x, Y, sig);

    (void)in_sizes; (void)n_in; (void)out_size;
}

// round 8
// speedup vs baseline: 3.6034x; 1.1294x over previous
#include <cuda_runtime.h>
#include <math.h>
#include <stdint.h>

#define Sd   2048
#define Hd   2048
#define NHd  16
#define Dd   128
#define Ed   8
#define IEd  1408
#define ISd  5632

// ---------------- static scratch (no allocations allowed) ----------------
__device__ float g_h1[Sd * Hd];
__device__ float g_q[Sd * Hd];
__device__ float g_k[Sd * Hd];
__device__ float g_v[Sd * Hd];
__device__ float g_scores[16 * 2048 * 2048];   // [NH, S, S]
__device__ float g_attn[Sd * Hd];
__device__ float g_h2[Sd * Hd];
__device__ float g_w[Sd * Ed];
__device__ int   g_cnt[Ed];
__device__ int   g_idx[Ed * Sd];
__device__ float g_G[Sd * IEd];
__device__ float g_U[Sd * IEd];
__device__ float g_Y[Sd * Hd];
__device__ float g_SG[Sd * ISd];
__device__ float g_SU[Sd * ISd];
__device__ float g_sig[Sd];

__device__ __forceinline__ uint32_t cvt_tf32(float f) {
    uint32_t r;
    asm("cvt.rna.tf32.f32 %0, %1;" : "=r"(r) : "f"(f));
    return r;
}

__device__ __forceinline__ void cpa16(uint32_t dst, const void* src) {
    asm volatile("cp.async.cg.shared.global [%0], [%1], 16;" :: "r"(dst), "l"(src));
}
#define CP_COMMIT() asm volatile("cp.async.commit_group;" ::: "memory")
#define CP_WAIT1()  asm volatile("cp.async.wait_group 1;" ::: "memory")

__device__ __forceinline__ void mma_tf32(float* c, const uint32_t* a, const uint32_t* b) {
    asm volatile(
        "mma.sync.aligned.m16n8k8.row.col.f32.tf32.tf32.f32 "
        "{%0,%1,%2,%3}, {%4,%5,%6,%7}, {%8,%9}, {%0,%1,%2,%3};\n"
        : "+f"(c[0]), "+f"(c[1]), "+f"(c[2]), "+f"(c[3])
        : "r"(a[0]), "r"(a[1]), "r"(a[2]), "r"(a[3]), "r"(b[0]), "r"(b[1]));
}

// ---------------- tf32 mma.sync GEMM: 128x128 tile, BK=32, cp.async 2-stage ----------------
// C[M,N] = A @ B.  A is [M,K] row-major (optionally row-gathered).
// BNK==true : B given as [N,K] row-major (scores GEMM, B^T semantics).
// BNK==false: B given as [K,N] row-major (weight matrices).
// causal==1: skip blocks fully above the diagonal.  causal==2: cap K at mBase+128.
template <bool BNK>
__global__ __launch_bounds__(256, 2)
void mgemm_kernel(const float* __restrict__ A, const float* __restrict__ B,
                  float* __restrict__ C,
                  int M, int N, int K, int lda, int ldb, int ldc,
                  long long sAz, long long sBz, long long sCz,
                  const float* __restrict__ bias,
                  const float* __restrict__ residual, int ldr,
                  const int* __restrict__ a_rows, const int* __restrict__ a_cnt,
                  int causal)
{
    const int mBase = blockIdx.y * 128;
    const int nBase = blockIdx.x * 128;
    if (causal == 1 && nBase >= mBase + 128) return;
    int count = M;
    if (a_cnt) { count = *a_cnt; if (count <= 0 || mBase >= count) return; }

    A += (long long)blockIdx.z * sAz;
    B += (long long)blockIdx.z * sBz;
    C += (long long)blockIdx.z * sCz;

    int kEnd = K;
    if (causal == 2) { int kl = mBase + 128; if (kl < kEnd) kEnd = kl; }
    const int nCh = kEnd >> 5;

    constexpr int ASZ = 128 * 36;                       // floats per A buffer
    constexpr int BSZ = BNK ? 128 * 36 : 32 * 136;      // floats per B buffer
    constexpr int STG = ASZ + BSZ;                      // buffer stride (floats)

    extern __shared__ float sm[];
    const uint32_t smU = (uint32_t)__cvta_generic_to_shared(sm);

    const int tid  = threadIdx.x;
    const int lane = tid & 31;
    const int wid  = tid >> 5;
    const int wm   = (wid >> 2) * 64;
    const int wn   = (wid & 3) * 32;
    const int gr   = lane >> 2;      // groupID
    const int tg   = lane & 3;       // threadID_in_group

    // ---- loader mapping ----
    const int ar0 = tid >> 3;                 // 0..31
    const int ac  = (tid & 7) * 4;            // 0..28
    const float* aPtr[4];
#pragma unroll
    for (int j = 0; j < 4; j++) {
        int r = mBase + ar0 + 32 * j;
        if (a_rows) r = a_rows[r < count ? r : count - 1];
        aPtr[j] = A + (long long)r * lda + ac;
    }
    const float* bPtr[4];
    int br0 = 0, bc = 0;
    if (BNK) {
#pragma unroll
        for (int j = 0; j < 4; j++)
            bPtr[j] = B + (long long)(nBase + ar0 + 32 * j) * ldb + ac;
    } else {
        br0 = tid >> 5;                       // 0..7
        bc  = (tid & 31) * 4;                 // 0..124
#pragma unroll
        for (int j = 0; j < 4; j++)
            bPtr[j] = B + (long long)(br0 + 8 * j) * ldb + nBase + bc;
    }

    const uint32_t aOff = (uint32_t)((ar0 * 36 + ac) * 4);      // thread A smem byte offset (j adds 32*36*4)
    const uint32_t bOff = BNK ? aOff
                              : (uint32_t)((br0 * 136 + bc) * 4);

    auto issue_chunk = [&](int c, int buf) {
        const int k0 = c << 5;
        const uint32_t base = smU + (uint32_t)(buf * STG * 4);
#pragma unroll
        for (int j = 0; j < 4; j++)
            cpa16(base + aOff + (uint32_t)(j * 32 * 36 * 4), aPtr[j] + k0);
        const uint32_t bbase = base + (uint32_t)(ASZ * 4);
        if (BNK) {
#pragma unroll
            for (int j = 0; j < 4; j++)
                cpa16(bbase + bOff + (uint32_t)(j * 32 * 36 * 4), bPtr[j] + k0);
        } else {
#pragma unroll
            for (int j = 0; j < 4; j++)
                cpa16(bbase + bOff + (uint32_t)(j * 8 * 136 * 4), bPtr[j] + (long long)k0 * ldb);
        }
    };

    float acc[4][4][4];
#pragma unroll
    for (int mi = 0; mi < 4; mi++)
#pragma unroll
        for (int ni = 0; ni < 4; ni++)
#pragma unroll
            for (int e = 0; e < 4; e++) acc[mi][ni][e] = 0.f;

    // prologue: chunk 0 into buffer 0
    issue_chunk(0, 0);
    CP_COMMIT();

    for (int c = 0; c < nCh; c++) {
        if (c + 1 < nCh) issue_chunk(c + 1, (c + 1) & 1);
        CP_COMMIT();
        CP_WAIT1();
        __syncthreads();

        const float* As = sm + (c & 1) * STG;
        const float* Bs = As + ASZ;

#pragma unroll
        for (int kk = 0; kk < 4; kk++) {
            const int ko = kk * 8;
            uint32_t af[4][4];
#pragma unroll
            for (int mi = 0; mi < 4; mi++) {
                const float* p = &As[(wm + mi * 16 + gr) * 36 + ko + tg];
                af[mi][0] = cvt_tf32(p[0]);
                af[mi][1] = cvt_tf32(p[8 * 36]);
                af[mi][2] = cvt_tf32(p[4]);
                af[mi][3] = cvt_tf32(p[8 * 36 + 4]);
            }
            uint32_t bf[4][2];
#pragma unroll
            for (int ni = 0; ni < 4; ni++) {
                if (BNK) {
                    const float* p = &Bs[(wn + ni * 8 + gr) * 36 + ko + tg];
                    bf[ni][0] = cvt_tf32(p[0]);
                    bf[ni][1] = cvt_tf32(p[4]);
                } else {
                    const float* p = &Bs[(ko + tg) * 136 + wn + ni * 8 + gr];
                    bf[ni][0] = cvt_tf32(p[0]);
                    bf[ni][1] = cvt_tf32(p[4 * 136]);
                }
            }
#pragma unroll
            for (int mi = 0; mi < 4; mi++)
#pragma unroll
                for (int ni = 0; ni < 4; ni++)
                    mma_tf32(acc[mi][ni], af[mi], bf[ni]);
        }
        __syncthreads();
    }

    // ---- epilogue ----
#pragma unroll
    for (int mi = 0; mi < 4; mi++) {
        const int gm0 = mBase + wm + mi * 16 + gr;
        const int gm1 = gm0 + 8;
        const bool ok0 = gm0 < count;
        const bool ok1 = gm1 < count;
#pragma unroll
        for (int ni = 0; ni < 4; ni++) {
            const int gn = nBase + wn + ni * 8 + tg * 2;
            float2 v0 = make_float2(acc[mi][ni][0], acc[mi][ni][1]);
            float2 v1 = make_float2(acc[mi][ni][2], acc[mi][ni][3]);
            if (bias) {
                float2 b = *(const float2*)(bias + gn);
                v0.x += b.x; v0.y += b.y; v1.x += b.x; v1.y += b.y;
            }
            if (ok0) {
                if (residual) {
                    float2 r = *(const float2*)(residual + (long long)gm0 * ldr + gn);
                    v0.x += r.x; v0.y += r.y;
                }
                *(float2*)(C + (long long)gm0 * ldc + gn) = v0;
            }
            if (ok1) {
                if (residual) {
                    float2 r = *(const float2*)(residual + (long long)gm1 * ldr + gn);
                    v1.x += r.x; v1.y += r.y;
                }
                *(float2*)(C + (long long)gm1 * ldc + gn) = v1;
            }
        }
    }
}

// ---------------- elementwise / reduction kernels ----------------
__global__ void reset_cnt_kernel(int* cnt)
{
    if (threadIdx.x < Ed) cnt[threadIdx.x] = 0;
}

__global__ void rmsnorm_kernel(const float* __restrict__ x, const float* __restrict__ w,
                               float* __restrict__ y)
{
    int s = blockIdx.x, tid = threadIdx.x;
    __shared__ float red[256];
    __shared__ float srs;
    const float* xr = x + (long long)s * Hd;
    float sum = 0.f;
    for (int h = tid; h < Hd; h += 256) { float v = xr[h]; sum += v * v; }
    red[tid] = sum; __syncthreads();
    for (int st = 128; st > 0; st >>= 1) {
        if (tid < st) red[tid] += red[tid + st];
        __syncthreads();
    }
    if (tid == 0) srs = rsqrtf(red[0] / (float)Hd + 1e-6f);
    __syncthreads();
    float rs = srs;
    float* yr = y + (long long)s * Hd;
    for (int h = tid; h < Hd; h += 256) yr[h] = w[h] * xr[h] * rs;
}

__global__ void rope_kernel(float* __restrict__ q, float* __restrict__ k)
{
    int i = blockIdx.x * 256 + threadIdx.x;
    int hi = i & 63;
    int h  = (i >> 6) & 15;
    int s  = i >> 10;
    float inv = powf(1000000.0f, -(float)hi / 64.0f);
    float ang = (float)s * inv;
    float sv, cv; sincosf(ang, &sv, &cv);
    long long base = (long long)s * Hd + h * Dd + hi;
    float q1 = q[base], q2 = q[base + 64];
    q[base]      = q1 * cv - q2 * sv;
    q[base + 64] = q2 * cv + q1 * sv;
    float k1 = k[base], k2 = k[base + 64];
    k[base]      = k1 * cv - k2 * sv;
    k[base + 64] = k2 * cv + k1 * sv;
}

__global__ void softmax_kernel(float* __restrict__ scores)
{
    int s = blockIdx.x, h = blockIdx.y, tid = threadIdx.x;
    float* row = scores + ((long long)h * Sd + s) * Sd;
    const float scale = 0.08838834764831845f;
    int limit = ((s >> 7) + 1) << 7;           // only [0, limit) is read by PV GEMM
    float r[8];
    float mx = -3.4e38f;
#pragma unroll
    for (int t = 0; t < 8; t++) {
        int kk = t * 256 + tid;
        float v = -3.4e38f;
        if (kk <= s) v = row[kk] * scale;
        r[t] = v; mx = fmaxf(mx, v);
    }
    __shared__ float red[256];
    red[tid] = mx; __syncthreads();
    for (int st = 128; st > 0; st >>= 1) {
        if (tid < st) red[tid] = fmaxf(red[tid], red[tid + st]);
        __syncthreads();
    }
    mx = red[0]; __syncthreads();
    float sum = 0.f;
#pragma unroll
    for (int t = 0; t < 8; t++) {
        int kk = t * 256 + tid;
        if (kk <= s) { r[t] = expf(r[t] - mx); sum += r[t]; }
        else r[t] = 0.f;
    }
    red[tid] = sum; __syncthreads();
    for (int st = 128; st > 0; st >>= 1) {
        if (tid < st) red[tid] += red[tid + st];
        __syncthreads();
    }
    float inv = 1.0f / red[0];
#pragma unroll
    for (int t = 0; t < 8; t++) {
        int kk = t * 256 + tid;
        if (kk < limit) row[kk] = r[t] * inv;
    }
}

__global__ void router_kernel(const float* __restrict__ h2, const float* __restrict__ gate_w,
                              float* __restrict__ logits_out, float* __restrict__ w_out,
                              int* __restrict__ cnt, int* __restrict__ idx)
{
    int s = blockIdx.x, tid = threadIdx.x;
    __shared__ float red[256][8];
    float loc[8];
#pragma unroll
    for (int e = 0; e < 8; e++) loc[e] = 0.f;
    const float* hr = h2 + (long long)s * Hd;
    for (int h = tid; h < Hd; h += 256) {
        float hv = hr[h];
#pragma unroll
        for (int e = 0; e < 8; e++) loc[e] += hv * gate_w[h * 8 + e];
    }
#pragma unroll
    for (int e = 0; e < 8; e++) red[tid][e] = loc[e];
    __syncthreads();
    for (int st = 128; st > 0; st >>= 1) {
        if (tid < st) {
#pragma unroll
            for (int e = 0; e < 8; e++) red[tid][e] += red[tid + st][e];
        }
        __syncthreads();
    }
    if (tid == 0) {
        float l[8], p[8], w[8];
        float mx = -3.4e38f;
#pragma unroll
        for (int e = 0; e < 8; e++) { l[e] = red[0][e]; logits_out[s * 8 + e] = l[e]; mx = fmaxf(mx, l[e]); }
        float sum = 0.f;
#pragma unroll
        for (int e = 0; e < 8; e++) { p[e] = expf(l[e] - mx); sum += p[e]; }
#pragma unroll
        for (int e = 0; e < 8; e++) { p[e] /= sum; w[e] = 0.f; }
        bool used[8] = {false, false, false, false, false, false, false, false};
        for (int t = 0; t < 4; t++) {
            int best = -1; float bv = -1.f;
            for (int e = 0; e < 8; e++)
                if (!used[e] && p[e] > bv) { bv = p[e]; best = e; }
            used[best] = true; w[best] = bv;
            int pos = atomicAdd(&cnt[best], 1);
            idx[best * Sd + pos] = s;
        }
#pragma unroll
        for (int e = 0; e < 8; e++) w_out[s * 8 + e] = w[e];
    }
}

__global__ void silu_mul_kernel(float* __restrict__ G, const float* __restrict__ U,
                                const int* __restrict__ cnt, int ncols)
{
    long long i = (long long)blockIdx.x * 256 + threadIdx.x;
    int r = (int)(i / ncols);
    if (cnt && r >= *cnt) return;
    float g = G[i], u = U[i];
    G[i] = (g / (1.f + expf(-g))) * u;
}

__global__ void scatter_kernel(float* __restrict__ out, const float* __restrict__ Y,
                               const float* __restrict__ w, const int* __restrict__ idx,
                               const int* __restrict__ cnt, int e)
{
    int i = blockIdx.x * 256 + threadIdx.x;
    int r = i >> 11, c = i & 2047;
    if (r >= cnt[e]) return;
    int s = idx[e * Sd + r];
    out[(long long)s * Hd + c] += w[s * Ed + e] * Y[i];
}

__global__ void sgate_kernel(const float* __restrict__ h2, const float* __restrict__ sgate,
                             float* __restrict__ sig)
{
    int s = blockIdx.x, tid = threadIdx.x;
    __shared__ float red[256];
    const float* hr = h2 + (long long)s * Hd;
    float sum = 0.f;
    for (int h = tid; h < Hd; h += 256) sum += hr[h] * sgate[h];
    red[tid] = sum; __syncthreads();
    for (int st = 128; st > 0; st >>= 1) {
        if (tid < st) red[tid] += red[tid + st];
        __syncthreads();
    }
    if (tid == 0) sig[s] = 1.f / (1.f + expf(-red[0]));
}

__global__ void add_shared_kernel(float* __restrict__ out, const float* __restrict__ Y,
                                  const float* __restrict__ sig)
{
    int i = blockIdx.x * 256 + threadIdx.x;
    int r = i >> 11;
    out[i] += sig[r] * Y[i];
}

// ---------------- host-side GEMM dispatch ----------------
static const int SMEM_T = 2 * (128 * 36 + 128 * 36) * 4;   // 73728 (BNK=true)
static const int SMEM_F = 2 * (128 * 36 + 32 * 136) * 4;   // 71680 (BNK=false)

static inline void tgemm(bool bnk, const float* A, const float* B, float* C,
                         int M, int N, int K, int lda, int ldb, int ldc,
                         long long sA = 0, long long sB = 0, long long sC = 0, int nz = 1,
                         const float* bias = nullptr,
                         const float* residual = nullptr, int ldr = 0,
                         const int* arows = nullptr, const int* acnt = nullptr,
                         int causal = 0)
{
    dim3 grid(N / 128, (M + 127) / 128, nz);
    if (bnk)
        mgemm_kernel<true><<<grid, 256, SMEM_T>>>(A, B, C, M, N, K, lda, ldb, ldc,
                                                  sA, sB, sC, bias, residual, ldr, arows, acnt, causal);
    else
        mgemm_kernel<false><<<grid, 256, SMEM_F>>>(A, B, C, M, N, K, lda, ldb, ldc,
                                                   sA, sB, sC, bias, residual, ldr, arows, acnt, causal);
}

extern "C" void kernel_launch(void* const* d_in, const int* in_sizes, int n_in,
                              void* d_out, int out_size)
{
    cudaFuncSetAttribute(mgemm_kernel<true>,  cudaFuncAttributeMaxDynamicSharedMemorySize, SMEM_T);
    cudaFuncSetAttribute(mgemm_kernel<false>, cudaFuncAttributeMaxDynamicSharedMemorySize, SMEM_F);

    const float* x     = (const float*)d_in[0];
    const float* ln1   = (const float*)d_in[1];
    const float* ln2   = (const float*)d_in[2];
    const float* wq    = (const float*)d_in[3];
    const float* bq    = (const float*)d_in[4];
    const float* wk    = (const float*)d_in[5];
    const float* bk    = (const float*)d_in[6];
    const float* wv    = (const float*)d_in[7];
    const float* bv    = (const float*)d_in[8];
    const float* wo    = (const float*)d_in[9];
    const float* gate  = (const float*)d_in[10];
    const float* eg    = (const float*)d_in[11];
    const float* eu    = (const float*)d_in[12];
    const float* ed    = (const float*)d_in[13];
    const float* sg    = (const float*)d_in[14];
    const float* su    = (const float*)d_in[15];
    const float* sd    = (const float*)d_in[16];
    const float* sgate = (const float*)d_in[17];

    float* out        = (float*)d_out;
    float* out_x      = out;                          // [S, H]
    float* out_logits = out + (long long)Sd * Hd;     // [S, E]

    float *h1, *q, *k, *v, *scores, *attn, *h2, *w, *G, *U, *Y, *SG, *SU, *sig;
    int *cnt, *idx;
    cudaGetSymbolAddress((void**)&h1,     g_h1);
    cudaGetSymbolAddress((void**)&q,      g_q);
    cudaGetSymbolAddress((void**)&k,      g_k);
    cudaGetSymbolAddress((void**)&v,      g_v);
    cudaGetSymbolAddress((void**)&scores, g_scores);
    cudaGetSymbolAddress((void**)&attn,   g_attn);
    cudaGetSymbolAddress((void**)&h2,     g_h2);
    cudaGetSymbolAddress((void**)&w,      g_w);
    cudaGetSymbolAddress((void**)&G,      g_G);
    cudaGetSymbolAddress((void**)&U,      g_U);
    cudaGetSymbolAddress((void**)&Y,      g_Y);
    cudaGetSymbolAddress((void**)&SG,     g_SG);
    cudaGetSymbolAddress((void**)&SU,     g_SU);
    cudaGetSymbolAddress((void**)&sig,    g_sig);
    cudaGetSymbolAddress((void**)&cnt,    g_cnt);
    cudaGetSymbolAddress((void**)&idx,    g_idx);

    // 0. reset expert counters
    reset_cnt_kernel<<<1, 32>>>(cnt);

    // 1. rmsnorm -> h1
    rmsnorm_kernel<<<Sd, 256>>>(x, ln1, h1);

    // 2. QKV projections (+bias)   [B is [K,N] -> BNK=false]
    tgemm(false, h1, wq, q, Sd, Hd, Hd, Hd, Hd, Hd, 0, 0, 0, 1, bq);
    tgemm(false, h1, wk, k, Sd, Hd, Hd, Hd, Hd, Hd, 0, 0, 0, 1, bk);
    tgemm(false, h1, wv, v, Sd, Hd, Hd, Hd, Hd, Hd, 0, 0, 0, 1, bv);

    // 3. RoPE (in place)
    rope_kernel<<<(Sd * NHd * 64) / 256, 256>>>(q, k);

    // 4. scores[h] = q_h @ k_h^T   [B is [N,K] -> BNK=true, causal block-skip]
    tgemm(true, q, k, scores, Sd, Sd, Dd, Hd, Hd, Sd,
          128, 128, (long long)Sd * Sd, NHd, nullptr, nullptr, 0, nullptr, nullptr, 1);

    // 5. causal softmax
    softmax_kernel<<<dim3(Sd, NHd), 256>>>(scores);

    // 6. attn[h] = probs_h @ v_h   [B is [K,N] -> BNK=false, K capped causally]
    tgemm(false, scores, v, attn, Sd, Dd, Sd, Sd, Hd, Hd,
          (long long)Sd * Sd, 128, 128, NHd, nullptr, nullptr, 0, nullptr, nullptr, 2);

    // 7. x2 = x + attn @ wo -> output buffer
    tgemm(false, attn, wo, out_x, Sd, Hd, Hd, Hd, Hd, Hd, 0, 0, 0, 1, nullptr, x, Hd);

    // 8. rmsnorm -> h2
    rmsnorm_kernel<<<Sd, 256>>>(out_x, ln2, h2);

    // 9. router
    router_kernel<<<Sd, 256>>>(h2, gate, out_logits, w, cnt, idx);

    // 10. routed MoE
    for (int e = 0; e < Ed; e++) {
        const float* ege = eg + (long long)e * Hd * IEd;
        const float* eue = eu + (long long)e * Hd * IEd;
        const float* ede = ed + (long long)e * IEd * Hd;
        tgemm(false, h2, ege, G, Sd, IEd, Hd, Hd, IEd, IEd, 0, 0, 0, 1,
              nullptr, nullptr, 0, idx + e * Sd, cnt + e, 0);
        tgemm(false, h2, eue, U, Sd, IEd, Hd, Hd, IEd, IEd, 0, 0, 0, 1,
              nullptr, nullptr, 0, idx + e * Sd, cnt + e, 0);
        silu_mul_kernel<<<(Sd * IEd) / 256, 256>>>(G, U, cnt + e, IEd);
        tgemm(false, G, ede, Y, Sd, Hd, IEd, IEd, Hd, Hd, 0, 0, 0, 1,
              nullptr, nullptr, 0, nullptr, cnt + e, 0);
        scatter_kernel<<<(Sd * Hd) / 256, 256>>>(out_x, Y, w, idx, cnt, e);
    }

    // 11. shared expert
    tgemm(false, h2, sg, SG, Sd, ISd, Hd, Hd, ISd, ISd);
    tgemm(false, h2, su, SU, Sd, ISd, Hd, Hd, ISd, ISd);
    silu_mul_kernel<<<(int)(((long long)Sd * ISd) / 256), 256>>>(SG, SU, nullptr, ISd);
    tgemm(false, SG, sd, Y, Sd, Hd, ISd, ISd, Hd, Hd);
    sgate_kernel<<<Sd, 256>>>(h2, sgate, sig);
    add_shared_kernel<<<(Sd * Hd) / 256, 256>>>(out_x, Y, sig);

    (void)in_sizes; (void)n_in; (void)out_size;
}

// round 12
// speedup vs baseline: 3.8558x; 1.0700x over previous
#include <cuda_runtime.h>
#include <math.h>
#include <stdint.h>

#define Sd   2048
#define Hd   2048
#define NHd  16
#define Dd   128
#define Ed   8
#define IEd  1408
#define ISd  5632

// ---------------- static scratch (no allocations allowed) ----------------
__device__ float g_h1[Sd * Hd];
__device__ float g_q[Sd * Hd];
__device__ float g_k[Sd * Hd];
__device__ float g_v[Sd * Hd];
__device__ float g_scores[16 * 2048 * 2048];   // [NH, S, S]
__device__ float g_attn[Sd * Hd];
__device__ float g_h2[Sd * Hd];
__device__ float g_h2x[Sd * Hd];               // exact (unrounded) h2 for router/sgate
__device__ float g_w[Sd * Ed];
__device__ int   g_cnt[Ed];
__device__ int   g_idx[Ed * Sd];
__device__ float g_G[Sd * IEd];
__device__ float g_U[Sd * IEd];
__device__ float g_Y[Sd * Hd];
__device__ float g_SG[Sd * ISd];
__device__ float g_SU[Sd * ISd];
__device__ float g_sig[Sd];
// transposed + tf32-rounded weights ([N,K] layouts)
__device__ float g_wqT[Hd * Hd];
__device__ float g_wkT[Hd * Hd];
__device__ float g_wvT[Hd * Hd];
__device__ float g_woT[Hd * Hd];
__device__ float g_egT[Ed * IEd * Hd];
__device__ float g_euT[Ed * IEd * Hd];
__device__ float g_edT[Ed * Hd * IEd];
__device__ float g_sgT[ISd * Hd];
__device__ float g_suT[ISd * Hd];
__device__ float g_sdT[Hd * ISd];

__device__ __forceinline__ uint32_t cvt_tf32(float f) {
    uint32_t r;
    asm("cvt.rna.tf32.f32 %0, %1;" : "=r"(r) : "f"(f));
    return r;
}
__device__ __forceinline__ float rnd_tf32(float f) { return __uint_as_float(cvt_tf32(f)); }

__device__ __forceinline__ void cpa16(uint32_t dst, const void* src) {
    asm volatile("cp.async.cg.shared.global [%0], [%1], 16;" :: "r"(dst), "l"(src));
}
#define CP_COMMIT() asm volatile("cp.async.commit_group;" ::: "memory")
#define CP_WAIT1()  asm volatile("cp.async.wait_group 1;" ::: "memory")

__device__ __forceinline__ void ldsm4(uint32_t* r, uint32_t addr) {
    asm volatile("ldmatrix.sync.aligned.m8n8.x4.shared.b16 {%0,%1,%2,%3}, [%4];"
        : "=r"(r[0]), "=r"(r[1]), "=r"(r[2]), "=r"(r[3]) : "r"(addr));
}

__device__ __forceinline__ void mma_tf32(float* c, const uint32_t* a, const uint32_t* b) {
    asm volatile(
        "mma.sync.aligned.m16n8k8.row.col.f32.tf32.tf32.f32 "
        "{%0,%1,%2,%3}, {%4,%5,%6,%7}, {%8,%9}, {%0,%1,%2,%3};\n"
        : "+f"(c[0]), "+f"(c[1]), "+f"(c[2]), "+f"(c[3])
        : "r"(a[0]), "r"(a[1]), "r"(a[2]), "r"(a[3]), "r"(b[0]), "r"(b[1]));
}

// ---------------- transpose + tf32-round: src[R,C] -> dst[C,R] ----------------
__global__ void trT_kernel(const float* __restrict__ src, float* __restrict__ dst, int R, int C)
{
    __shared__ float t[32][33];
    const int bx = blockIdx.x * 32;   // C
    const int by = blockIdx.y * 32;   // R
    const long long zo = (long long)blockIdx.z * R * C;
    const int tx = threadIdx.x, ty = threadIdx.y;
#pragma unroll
    for (int j = 0; j < 32; j += 8)
        t[ty + j][tx] = src[zo + (long long)(by + ty + j) * C + bx + tx];
    __syncthreads();
#pragma unroll
    for (int j = 0; j < 32; j += 8)
        dst[zo + (long long)(bx + ty + j) * R + by + tx] = rnd_tf32(t[tx][ty + j]);
}

// ---------------- tf32 mma.sync GEMM: 128x128 tile, BK=32, cp.async 2-stage ----------------
// C[M,N] = A @ B.  A is [M,K] row-major tf32-rounded (optionally row-gathered).
// BNK==true : B given as [N,K] row-major (pre-rounded); ldmatrix frags for A and B.
// BNK==false: B given as [K,N] row-major (PV GEMM); scalar B frags.
// causal==1: skip blocks fully above diagonal.  causal==2: cap K at mBase+128.
template <bool BNK>
__global__ __launch_bounds__(256, 2)
void mgemm_kernel(const float* __restrict__ A, const float* __restrict__ B,
                  float* __restrict__ C,
                  int M, int N, int K, int lda, int ldb, int ldc,
                  long long sAz, long long sBz, long long sCz,
                  const float* __restrict__ bias,
                  const float* __restrict__ residual, int ldr,
                  const int* __restrict__ a_rows, const int* __restrict__ a_cnt,
                  int causal, int roundOut)
{
    const int mBase = blockIdx.y * 128;
    const int nBase = blockIdx.x * 128;
    if (causal == 1 && nBase >= mBase + 128) return;
    int count = M;
    if (a_cnt) { count = *a_cnt; if (count <= 0 || mBase >= count) return; }

    A += (long long)blockIdx.z * sAz;
    B += (long long)blockIdx.z * sBz;
    C += (long long)blockIdx.z * sCz;

    int kEnd = K;
    if (causal == 2) { int kl = mBase + 128; if (kl < kEnd) kEnd = kl; }
    const int nCh = kEnd >> 5;

    constexpr int ASZ = 128 * 36;
    constexpr int BSZ = BNK ? 128 * 36 : 32 * 136;
    constexpr int STG = ASZ + BSZ;

    extern __shared__ float sm[];
    const uint32_t smU = (uint32_t)__cvta_generic_to_shared(sm);

    const int tid  = threadIdx.x;
    const int lane = tid & 31;
    const int wid  = tid >> 5;
    const int wm   = (wid >> 2) * 64;
    const int wn   = (wid & 3) * 32;
    const int gr   = lane >> 2;
    const int tg   = lane & 3;

    // ---- cp.async loader mapping ----
    const int ar0 = tid >> 3;                 // 0..31
    const int ac  = (tid & 7) * 4;            // 0..28
    const float* aPtr[4];
#pragma unroll
    for (int j = 0; j < 4; j++) {
        int r = mBase + ar0 + 32 * j;
        if (a_rows) r = a_rows[r < count ? r : count - 1];
        aPtr[j] = A + (long long)r * lda + ac;
    }
    const float* bPtr[4];
    int br0 = 0, bc = 0;
    if (BNK) {
#pragma unroll
        for (int j = 0; j < 4; j++)
            bPtr[j] = B + (long long)(nBase + ar0 + 32 * j) * ldb + ac;
    } else {
        br0 = tid >> 5;
        bc  = (tid & 31) * 4;
#pragma unroll
        for (int j = 0; j < 4; j++)
            bPtr[j] = B + (long long)(br0 + 8 * j) * ldb + nBase + bc;
    }

    const uint32_t aOff = (uint32_t)((ar0 * 36 + ac) * 4);
    const uint32_t bOff = BNK ? aOff : (uint32_t)((br0 * 136 + bc) * 4);

    auto issue_chunk = [&](int c, int buf) {
        const int k0 = c << 5;
        const uint32_t base = smU + (uint32_t)(buf * STG * 4);
#pragma unroll
        for (int j = 0; j < 4; j++)
            cpa16(base + aOff + (uint32_t)(j * 32 * 36 * 4), aPtr[j] + k0);
        const uint32_t bbase = base + (uint32_t)(ASZ * 4);
        if (BNK) {
#pragma unroll
            for (int j = 0; j < 4; j++)
                cpa16(bbase + bOff + (uint32_t)(j * 32 * 36 * 4), bPtr[j] + k0);
        } else {
#pragma unroll
            for (int j = 0; j < 4; j++)
                cpa16(bbase + bOff + (uint32_t)(j * 8 * 136 * 4), bPtr[j] + (long long)k0 * ldb);
        }
    };

    // ---- ldmatrix fragment addresses (per-thread, buffer 0, byte units) ----
    // A x4: matrices (m-half, k-half): rows wm + (m&1)*8 + r, cols (m>>1)*4.
    const int t8 = lane & 7;
    const uint32_t aFrag = smU +
        (uint32_t)(((wm + ((lane >> 3) & 1) * 8 + t8) * 36 + (lane >> 4) * 4) * 4);
    // B x4 (BNK): matrices (n-half, k-half): rows wn + (m>>1)*8 + r, cols (m&1)*4.
    const uint32_t bFrag = smU + (uint32_t)(ASZ * 4) +
        (uint32_t)(((wn + (lane >> 4) * 8 + t8) * 36 + ((lane >> 3) & 1) * 4) * 4);

    float acc[4][4][4];
#pragma unroll
    for (int mi = 0; mi < 4; mi++)
#pragma unroll
        for (int ni = 0; ni < 4; ni++)
#pragma unroll
            for (int e = 0; e < 4; e++) acc[mi][ni][e] = 0.f;

    issue_chunk(0, 0);
    CP_COMMIT();

    for (int c = 0; c < nCh; c++) {
        if (c + 1 < nCh) issue_chunk(c + 1, (c + 1) & 1);
        CP_COMMIT();
        CP_WAIT1();
        __syncthreads();

        const uint32_t bufB = (uint32_t)((c & 1) * STG * 4);
        const float* Bs = sm + (c & 1) * STG + ASZ;

#pragma unroll
        for (int kk = 0; kk < 4; kk++) {
            const int ko = kk * 8;
            uint32_t af[4][4];
#pragma unroll
            for (int mi = 0; mi < 4; mi++)
                ldsm4(af[mi], aFrag + bufB + (uint32_t)((mi * 16 * 36 + ko) * 4));
            uint32_t bf[4][2];
            if (BNK) {
                uint32_t r4[4];
                ldsm4(r4, bFrag + bufB + (uint32_t)(ko * 4));
                bf[0][0] = r4[0]; bf[0][1] = r4[1]; bf[1][0] = r4[2]; bf[1][1] = r4[3];
                ldsm4(r4, bFrag + bufB + (uint32_t)((16 * 36 + ko) * 4));
                bf[2][0] = r4[0]; bf[2][1] = r4[1]; bf[3][0] = r4[2]; bf[3][1] = r4[3];
            } else {
#pragma unroll
                for (int ni = 0; ni < 4; ni++) {
                    const float* p = &Bs[(ko + tg) * 136 + wn + ni * 8 + gr];
                    bf[ni][0] = __float_as_uint(p[0]);
                    bf[ni][1] = __float_as_uint(p[4 * 136]);
                }
            }
#pragma unroll
            for (int mi = 0; mi < 4; mi++)
#pragma unroll
                for (int ni = 0; ni < 4; ni++)
                    mma_tf32(acc[mi][ni], af[mi], bf[ni]);
        }
        __syncthreads();
    }

    // ---- epilogue ----
#pragma unroll
    for (int mi = 0; mi < 4; mi++) {
        const int gm0 = mBase + wm + mi * 16 + gr;
        const int gm1 = gm0 + 8;
        const bool ok0 = gm0 < count;
        const bool ok1 = gm1 < count;
#pragma unroll
        for (int ni = 0; ni < 4; ni++) {
            const int gn = nBase + wn + ni * 8 + tg * 2;
            float2 v0 = make_float2(acc[mi][ni][0], acc[mi][ni][1]);
            float2 v1 = make_float2(acc[mi][ni][2], acc[mi][ni][3]);
            if (bias) {
                float2 b = *(const float2*)(bias + gn);
                v0.x += b.x; v0.y += b.y; v1.x += b.x; v1.y += b.y;
            }
            if (roundOut) {
                v0.x = rnd_tf32(v0.x); v0.y = rnd_tf32(v0.y);
                v1.x = rnd_tf32(v1.x); v1.y = rnd_tf32(v1.y);
            }
            if (ok0) {
                if (residual) {
                    float2 r = *(const float2*)(residual + (long long)gm0 * ldr + gn);
                    v0.x += r.x; v0.y += r.y;
                }
                *(float2*)(C + (long long)gm0 * ldc + gn) = v0;
            }
            if (ok1) {
                if (residual) {
                    float2 r = *(const float2*)(residual + (long long)gm1 * ldr + gn);
                    v1.x += r.x; v1.y += r.y;
                }
                *(float2*)(C + (long long)gm1 * ldc + gn) = v1;
            }
        }
    }
}

// ---------------- elementwise / reduction kernels ----------------
__global__ void reset_cnt_kernel(int* cnt)
{
    if (threadIdx.x < Ed) cnt[threadIdx.x] = 0;
}

// y = tf32-rounded rmsnorm; y2 (optional) = exact rmsnorm
__global__ void rmsnorm_kernel(const float* __restrict__ x, const float* __restrict__ w,
                               float* __restrict__ y, float* __restrict__ y2)
{
    int s = blockIdx.x, tid = threadIdx.x;
    __shared__ float red[256];
    __shared__ float srs;
    const float* xr = x + (long long)s * Hd;
    float sum = 0.f;
    for (int h = tid; h < Hd; h += 256) { float v = xr[h]; sum += v * v; }
    red[tid] = sum; __syncthreads();
    for (int st = 128; st > 0; st >>= 1) {
        if (tid < st) red[tid] += red[tid + st];
        __syncthreads();
    }
    if (tid == 0) srs = rsqrtf(red[0] / (float)Hd + 1e-6f);
    __syncthreads();
    float rs = srs;
    float* yr = y + (long long)s * Hd;
    float* y2r = y2 ? y2 + (long long)s * Hd : nullptr;
    for (int h = tid; h < Hd; h += 256) {
        float v = w[h] * xr[h] * rs;
        yr[h] = rnd_tf32(v);
        if (y2r) y2r[h] = v;
    }
}

__global__ void rope_kernel(float* __restrict__ q, float* __restrict__ k)
{
    int i = blockIdx.x * 256 + threadIdx.x;
    int hi = i & 63;
    int h  = (i >> 6) & 15;
    int s  = i >> 10;
    float inv = powf(1000000.0f, -(float)hi / 64.0f);
    float ang = (float)s * inv;
    float sv, cv; sincosf(ang, &sv, &cv);
    long long base = (long long)s * Hd + h * Dd + hi;
    float q1 = q[base], q2 = q[base + 64];
    q[base]      = rnd_tf32(q1 * cv - q2 * sv);
    q[base + 64] = rnd_tf32(q2 * cv + q1 * sv);
    float k1 = k[base], k2 = k[base + 64];
    k[base]      = rnd_tf32(k1 * cv - k2 * sv);
    k[base + 64] = rnd_tf32(k2 * cv + k1 * sv);
}

__global__ void softmax_kernel(float* __restrict__ scores)
{
    int s = blockIdx.x, h = blockIdx.y, tid = threadIdx.x;
    float* row = scores + ((long long)h * Sd + s) * Sd;
    const float scale = 0.08838834764831845f;
    int limit = ((s >> 7) + 1) << 7;           // only [0, limit) is read by PV GEMM
    float r[8];
    float mx = -3.4e38f;
#pragma unroll
    for (int t = 0; t < 8; t++) {
        int kk = t * 256 + tid;
        float v = -3.4e38f;
        if (kk <= s) v = row[kk] * scale;
        r[t] = v; mx = fmaxf(mx, v);
    }
    __shared__ float red[256];
    red[tid] = mx; __syncthreads();
    for (int st = 128; st > 0; st >>= 1) {
        if (tid < st) red[tid] = fmaxf(red[tid], red[tid + st]);
        __syncthreads();
    }
    mx = red[0]; __syncthreads();
    float sum = 0.f;
#pragma unroll
    for (int t = 0; t < 8; t++) {
        int kk = t * 256 + tid;
        if (kk <= s) { r[t] = expf(r[t] - mx); sum += r[t]; }
        else r[t] = 0.f;
    }
    red[tid] = sum; __syncthreads();
    for (int st = 128; st > 0; st >>= 1) {
        if (tid < st) red[tid] += red[tid + st];
        __syncthreads();
    }
    float inv = 1.0f / red[0];
#pragma unroll
    for (int t = 0; t < 8; t++) {
        int kk = t * 256 + tid;
        if (kk < limit) row[kk] = rnd_tf32(r[t] * inv);
    }
}

__global__ void router_kernel(const float* __restrict__ h2, const float* __restrict__ gate_w,
                              float* __restrict__ logits_out, float* __restrict__ w_out,
                              int* __restrict__ cnt, int* __restrict__ idx)
{
    int s = blockIdx.x, tid = threadIdx.x;
    __shared__ float red[256][8];
    float loc[8];
#pragma unroll
    for (int e = 0; e < 8; e++) loc[e] = 0.f;
    const float* hr = h2 + (long long)s * Hd;
    for (int h = tid; h < Hd; h += 256) {
        float hv = hr[h];
#pragma unroll
        for (int e = 0; e < 8; e++) loc[e] += hv * gate_w[h * 8 + e];
    }
#pragma unroll
    for (int e = 0; e < 8; e++) red[tid][e] = loc[e];
    __syncthreads();
    for (int st = 128; st > 0; st >>= 1) {
        if (tid < st) {
#pragma unroll
            for (int e = 0; e < 8; e++) red[tid][e] += red[tid + st][e];
        }
        __syncthreads();
    }
    if (tid == 0) {
        float l[8], p[8], w[8];
        float mx = -3.4e38f;
#pragma unroll
        for (int e = 0; e < 8; e++) { l[e] = red[0][e]; logits_out[s * 8 + e] = l[e]; mx = fmaxf(mx, l[e]); }
        float sum = 0.f;
#pragma unroll
        for (int e = 0; e < 8; e++) { p[e] = expf(l[e] - mx); sum += p[e]; }
#pragma unroll
        for (int e = 0; e < 8; e++) { p[e] /= sum; w[e] = 0.f; }
        bool used[8] = {false, false, false, false, false, false, false, false};
        for (int t = 0; t < 4; t++) {
            int best = -1; float bv = -1.f;
            for (int e = 0; e < 8; e++)
                if (!used[e] && p[e] > bv) { bv = p[e]; best = e; }
            used[best] = true; w[best] = bv;
            int pos = atomicAdd(&cnt[best], 1);
            idx[best * Sd + pos] = s;
        }
#pragma unroll
        for (int e = 0; e < 8; e++) w_out[s * 8 + e] = w[e];
    }
}

__global__ void silu_mul_kernel(float* __restrict__ G, const float* __restrict__ U,
                                const int* __restrict__ cnt, int ncols)
{
    long long i = (long long)blockIdx.x * 256 + threadIdx.x;
    int r = (int)(i / ncols);
    if (cnt && r >= *cnt) return;
    float g = G[i], u = U[i];
    G[i] = rnd_tf32((g / (1.f + expf(-g))) * u);
}

__global__ void scatter_kernel(float* __restrict__ out, const float* __restrict__ Y,
                               const float* __restrict__ w, const int* __restrict__ idx,
                               const int* __restrict__ cnt, int e)
{
    int i = blockIdx.x * 256 + threadIdx.x;
    int r = i >> 11, c = i & 2047;
    if (r >= cnt[e]) return;
    int s = idx[e * Sd + r];
    out[(long long)s * Hd + c] += w[s * Ed + e] * Y[i];
}

__global__ void sgate_kernel(const float* __restrict__ h2, const float* __restrict__ sgate,
                             float* __restrict__ sig)
{
    int s = blockIdx.x, tid = threadIdx.x;
    __shared__ float red[256];
    const float* hr = h2 + (long long)s * Hd;
    float sum = 0.f;
    for (int h = tid; h < Hd; h += 256) sum += hr[h] * sgate[h];
    red[tid] = sum; __syncthreads();
    for (int st = 128; st > 0; st >>= 1) {
        if (tid < st) red[tid] += red[tid + st];
        __syncthreads();
    }
    if (tid == 0) sig[s] = 1.f / (1.f + expf(-red[0]));
}

__global__ void add_shared_kernel(float* __restrict__ out, const float* __restrict__ Y,
                                  const float* __restrict__ sig)
{
    int i = blockIdx.x * 256 + threadIdx.x;
    int r = i >> 11;
    out[i] += sig[r] * Y[i];
}

// ---------------- host-side GEMM dispatch ----------------
static const int SMEM_T = 2 * (128 * 36 + 128 * 36) * 4;   // 73728 (BNK=true)
static const int SMEM_F = 2 * (128 * 36 + 32 * 136) * 4;   // 71680 (BNK=false)

static inline void tgemm(bool bnk, const float* A, const float* B, float* C,
                         int M, int N, int K, int lda, int ldb, int ldc,
                         long long sA = 0, long long sB = 0, long long sC = 0, int nz = 1,
                         const float* bias = nullptr,
                         const float* residual = nullptr, int ldr = 0,
                         const int* arows = nullptr, const int* acnt = nullptr,
                         int causal = 0, int roundOut = 0)
{
    dim3 grid(N / 128, (M + 127) / 128, nz);
    if (bnk)
        mgemm_kernel<true><<<grid, 256, SMEM_T>>>(A, B, C, M, N, K, lda, ldb, ldc,
                                                  sA, sB, sC, bias, residual, ldr, arows, acnt, causal, roundOut);
    else
        mgemm_kernel<false><<<grid, 256, SMEM_F>>>(A, B, C, M, N, K, lda, ldb, ldc,
                                                   sA, sB, sC, bias, residual, ldr, arows, acnt, causal, roundOut);
}

static inline void trT(const float* src, float* dst, int R, int C, int nz)
{
    dim3 grid(C / 32, R / 32, nz);
    trT_kernel<<<grid, dim3(32, 8)>>>(src, dst, R, C);
}

extern "C" void kernel_launch(void* const* d_in, const int* in_sizes, int n_in,
                              void* d_out, int out_size)
{
    cudaFuncSetAttribute(mgemm_kernel<true>,  cudaFuncAttributeMaxDynamicSharedMemorySize, SMEM_T);
    cudaFuncSetAttribute(mgemm_kernel<false>, cudaFuncAttributeMaxDynamicSharedMemorySize, SMEM_F);

    const float* x     = (const float*)d_in[0];
    const float* ln1   = (const float*)d_in[1];
    const float* ln2   = (const float*)d_in[2];
    const float* wq    = (const float*)d_in[3];
    const float* bq    = (const float*)d_in[4];
    const float* wk    = (const float*)d_in[5];
    const float* bk    = (const float*)d_in[6];
    const float* wv    = (const float*)d_in[7];
    const float* bv    = (const float*)d_in[8];
    const float* wo    = (const float*)d_in[9];
    const float* gate  = (const float*)d_in[10];
    const float* eg    = (const float*)d_in[11];
    const float* eu    = (const float*)d_in[12];
    const float* ed    = (const float*)d_in[13];
    const float* sg    = (const float*)d_in[14];
    const float* su    = (const float*)d_in[15];
    const float* sd    = (const float*)d_in[16];
    const float* sgate = (const float*)d_in[17];

    float* out        = (float*)d_out;
    float* out_x      = out;                          // [S, H]
    float* out_logits = out + (long long)Sd * Hd;     // [S, E]

    float *h1, *q, *k, *v, *scores, *attn, *h2, *h2x, *w, *G, *U, *Y, *SG, *SU, *sig;
    float *wqT, *wkT, *wvT, *woT, *egT, *euT, *edT, *sgT, *suT, *sdT;
    int *cnt, *idx;
    cudaGetSymbolAddress((void**)&h1,     g_h1);
    cudaGetSymbolAddress((void**)&q,      g_q);
    cudaGetSymbolAddress((void**)&k,      g_k);
    cudaGetSymbolAddress((void**)&v,      g_v);
    cudaGetSymbolAddress((void**)&scores, g_scores);
    cudaGetSymbolAddress((void**)&attn,   g_attn);
    cudaGetSymbolAddress((void**)&h2,     g_h2);
    cudaGetSymbolAddress((void**)&h2x,    g_h2x);
    cudaGetSymbolAddress((void**)&w,      g_w);
    cudaGetSymbolAddress((void**)&G,      g_G);
    cudaGetSymbolAddress((void**)&U,      g_U);
    cudaGetSymbolAddress((void**)&Y,      g_Y);
    cudaGetSymbolAddress((void**)&SG,     g_SG);
    cudaGetSymbolAddress((void**)&SU,     g_SU);
    cudaGetSymbolAddress((void**)&sig,    g_sig);
    cudaGetSymbolAddress((void**)&cnt,    g_cnt);
    cudaGetSymbolAddress((void**)&idx,    g_idx);
    cudaGetSymbolAddress((void**)&wqT,    g_wqT);
    cudaGetSymbolAddress((void**)&wkT,    g_wkT);
    cudaGetSymbolAddress((void**)&wvT,    g_wvT);
    cudaGetSymbolAddress((void**)&woT,    g_woT);
    cudaGetSymbolAddress((void**)&egT,    g_egT);
    cudaGetSymbolAddress((void**)&euT,    g_euT);
    cudaGetSymbolAddress((void**)&edT,    g_edT);
    cudaGetSymbolAddress((void**)&sgT,    g_sgT);
    cudaGetSymbolAddress((void**)&suT,    g_suT);
    cudaGetSymbolAddress((void**)&sdT,    g_sdT);

    // 0. weight transpose + tf32 rounding (one pass per launch)
    trT(wq, wqT, Hd, Hd, 1);
    trT(wk, wkT, Hd, Hd, 1);
    trT(wv, wvT, Hd, Hd, 1);
    trT(wo, woT, Hd, Hd, 1);
    trT(eg, egT, Hd, IEd, Ed);
    trT(eu, euT, Hd, IEd, Ed);
    trT(ed, edT, IEd, Hd, Ed);
    trT(sg, sgT, Hd, ISd, 1);
    trT(su, suT, Hd, ISd, 1);
    trT(sd, sdT, ISd, Hd, 1);

    reset_cnt_kernel<<<1, 32>>>(cnt);

    // 1. rmsnorm -> h1 (rounded)
    rmsnorm_kernel<<<Sd, 256>>>(x, ln1, h1, nullptr);

    // 2. QKV projections (+bias); v output rounded (PV operand)
    tgemm(true, h1, wqT, q, Sd, Hd, Hd, Hd, Hd, Hd, 0, 0, 0, 1, bq);
    tgemm(true, h1, wkT, k, Sd, Hd, Hd, Hd, Hd, Hd, 0, 0, 0, 1, bk);
    tgemm(true, h1, wvT, v, Sd, Hd, Hd, Hd, Hd, Hd, 0, 0, 0, 1, bv,
          nullptr, 0, nullptr, nullptr, 0, 1);

    // 3. RoPE (in place, rounded outputs)
    rope_kernel<<<(Sd * NHd * 64) / 256, 256>>>(q, k);

    // 4. scores[h] = q_h @ k_h^T   (k rows are [N,K]; causal block-skip)
    tgemm(true, q, k, scores, Sd, Sd, Dd, Hd, Hd, Sd,
          128, 128, (long long)Sd * Sd, NHd, nullptr, nullptr, 0, nullptr, nullptr, 1);

    // 5. causal softmax (rounded probs)
    softmax_kernel<<<dim3(Sd, NHd), 256>>>(scores);

    // 6. attn[h] = probs_h @ v_h  (B=[K,N]; K capped; output rounded for WO GEMM)
    tgemm(false, scores, v, attn, Sd, Dd, Sd, Sd, Hd, Hd,
          (long long)Sd * Sd, 128, 128, NHd, nullptr, nullptr, 0, nullptr, nullptr, 2, 1);

    // 7. x2 = x + attn @ wo -> output buffer
    tgemm(true, attn, woT, out_x, Sd, Hd, Hd, Hd, Hd, Hd, 0, 0, 0, 1, nullptr, x, Hd);

    // 8. rmsnorm -> h2 (rounded) + h2x (exact for router/sgate)
    rmsnorm_kernel<<<Sd, 256>>>(out_x, ln2, h2, h2x);

    // 9. router (exact h2)
    router_kernel<<<Sd, 256>>>(h2x, gate, out_logits, w, cnt, idx);

    // 10. routed MoE
    for (int e = 0; e < Ed; e++) {
        const float* egTe = egT + (long long)e * IEd * Hd;
        const float* euTe = euT + (long long)e * IEd * Hd;
        const float* edTe = edT + (long long)e * Hd * IEd;
        tgemm(true, h2, egTe, G, Sd, IEd, Hd, Hd, Hd, IEd, 0, 0, 0, 1,
              nullptr, nullptr, 0, idx + e * Sd, cnt + e, 0);
        tgemm(true, h2, euTe, U, Sd, IEd, Hd, Hd, Hd, IEd, 0, 0, 0, 1,
              nullptr, nullptr, 0, idx + e * Sd, cnt + e, 0);
        silu_mul_kernel<<<(Sd * IEd) / 256, 256>>>(G, U, cnt + e, IEd);
        tgemm(true, G, edTe, Y, Sd, Hd, IEd, IEd, IEd, Hd, 0, 0, 0, 1,
              nullptr, nullptr, 0, nullptr, cnt + e, 0);
        scatter_kernel<<<(Sd * Hd) / 256, 256>>>(out_x, Y, w, idx, cnt, e);
    }

    // 11. shared expert
    tgemm(true, h2, sgT, SG, Sd, ISd, Hd, Hd, Hd, ISd);
    tgemm(true, h2, suT, SU, Sd, ISd, Hd, Hd, Hd, ISd);
    silu_mul_kernel<<<(int)(((long long)Sd * ISd) / 256), 256>>>(SG, SU, nullptr, ISd);
    tgemm(true, SG, sdT, Y, Sd, Hd, ISd, ISd, ISd, Hd);
    sgate_kernel<<<Sd, 256>>>(h2x, sgate, sig);
    add_shared_kernel<<<(Sd * Hd) / 256, 256>>>(out_x, Y, sig);

    (void)in_sizes; (void)n_in; (void)out_size;
}

// round 13
// speedup vs baseline: 5.0673x; 1.3142x over previous
#include <cuda_runtime.h>
#include <math.h>
#include <stdint.h>

#define Sd   2048
#define Hd   2048
#define NHd  16
#define Dd   128
#define Ed   8
#define IEd  1408
#define ISd  5632
#define QKVW 6144            // 3*Hd
#define GUW  2816            // 2*IEd
#define SGW  11264           // 2*ISd

// ---------------- static scratch ----------------
__device__ float g_h1[Sd * Hd];
__device__ float g_qkv[Sd * QKVW];
__device__ float g_scores[16 * 2048 * 2048];
__device__ float g_attn[Sd * Hd];
__device__ float g_h2[Sd * Hd];
__device__ float g_h2x[Sd * Hd];
__device__ int   g_cnt[Ed];
__device__ int   g_idx[Ed * Sd];
__device__ float g_w4[Sd * 4];
__device__ int   g_sel4[Sd * 4];
__device__ int   g_pos4[Sd * 4];
__device__ float g_GU[(long long)Ed * Sd * GUW];
__device__ float g_Ye[(long long)Ed * Sd * Hd];
__device__ float g_SGU[(long long)Sd * SGW];
__device__ float g_Ysh[Sd * Hd];
__device__ float g_sig[Sd];
__device__ float g_bqkv[QKVW];
// transposed + tf32-rounded weights ([N,K])
__device__ float g_qkvT[(long long)QKVW * Hd];
__device__ float g_woT[Hd * Hd];
__device__ float g_guT[(long long)Ed * GUW * Hd];
__device__ float g_edT[(long long)Ed * Hd * IEd];
__device__ float g_sguT[(long long)SGW * Hd];
__device__ float g_sdT[(long long)Hd * ISd];

__device__ __forceinline__ uint32_t cvt_tf32(float f) {
    uint32_t r;
    asm("cvt.rna.tf32.f32 %0, %1;" : "=r"(r) : "f"(f));
    return r;
}
__device__ __forceinline__ float rnd_tf32(float f) { return __uint_as_float(cvt_tf32(f)); }

__device__ __forceinline__ void cpa16(uint32_t dst, const void* src) {
    asm volatile("cp.async.cg.shared.global [%0], [%1], 16;" :: "r"(dst), "l"(src));
}
#define CP_COMMIT() asm volatile("cp.async.commit_group;" ::: "memory")
#define CP_WAIT1()  asm volatile("cp.async.wait_group 1;" ::: "memory")

__device__ __forceinline__ void ldsm4(uint32_t* r, uint32_t addr) {
    asm volatile("ldmatrix.sync.aligned.m8n8.x4.shared.b16 {%0,%1,%2,%3}, [%4];"
        : "=r"(r[0]), "=r"(r[1]), "=r"(r[2]), "=r"(r[3]) : "r"(addr));
}

__device__ __forceinline__ void mma_tf32(float* c, const uint32_t* a, const uint32_t* b) {
    asm volatile(
        "mma.sync.aligned.m16n8k8.row.col.f32.tf32.tf32.f32 "
        "{%0,%1,%2,%3}, {%4,%5,%6,%7}, {%8,%9}, {%0,%1,%2,%3};\n"
        : "+f"(c[0]), "+f"(c[1]), "+f"(c[2]), "+f"(c[3])
        : "r"(a[0]), "r"(a[1]), "r"(a[2]), "r"(a[3]), "r"(b[0]), "r"(b[1]));
}

// ---------------- transpose + tf32-round: src[R,C](z: R*C) -> dst[C,R](z: dstZ) ----------------
__global__ void trT_kernel(const float* __restrict__ src, float* __restrict__ dst,
                           int R, int C, long long dstZ)
{
    __shared__ float t[32][33];
    const int bx = blockIdx.x * 32;   // C
    const int by = blockIdx.y * 32;   // R
    const long long zs = (long long)blockIdx.z * R * C;
    const long long zd = (long long)blockIdx.z * dstZ;
    const int tx = threadIdx.x, ty = threadIdx.y;
#pragma unroll
    for (int j = 0; j < 32; j += 8)
        t[ty + j][tx] = src[zs + (long long)(by + ty + j) * C + bx + tx];
    __syncthreads();
#pragma unroll
    for (int j = 0; j < 32; j += 8)
        dst[zd + (long long)(bx + ty + j) * R + by + tx] = rnd_tf32(t[tx][ty + j]);
}

__global__ void bias_cat_kernel(const float* __restrict__ bq, const float* __restrict__ bk,
                                const float* __restrict__ bv, float* __restrict__ b)
{
    int i = blockIdx.x * 256 + threadIdx.x;
    b[i] = (i < 2048) ? bq[i] : (i < 4096 ? bk[i - 2048] : bv[i - 4096]);
}

// ---------------- tf32 mma.sync GEMM: 128x128 tile, BK=32, cp.async 3-stage ----------------
template <bool BNK>
__global__ __launch_bounds__(256, 2)
void mgemm_kernel(const float* __restrict__ A, const float* __restrict__ B,
                  float* __restrict__ C,
                  int M, int N, int K, int lda, int ldb, int ldc,
                  long long sAz, long long sBz, long long sCz,
                  const float* __restrict__ bias,
                  const float* __restrict__ residual, int ldr,
                  const int* __restrict__ a_rows, const int* __restrict__ a_cnt,
                  int causal, int roundOut, int perZ)
{
    const int mBase = blockIdx.y * 128;
    const int nBase = blockIdx.x * 128;
    if (causal == 1 && nBase >= mBase + 128) return;
    int count = M;
    if (a_cnt) {
        count = perZ ? a_cnt[blockIdx.z] : *a_cnt;
        if (count <= 0 || mBase >= count) return;
    }
    if (a_rows && perZ) a_rows += blockIdx.z * Sd;

    A += (long long)blockIdx.z * sAz;
    B += (long long)blockIdx.z * sBz;
    C += (long long)blockIdx.z * sCz;

    int kEnd = K;
    if (causal == 2) { int kl = mBase + 128; if (kl < kEnd) kEnd = kl; }
    const int nCh = kEnd >> 5;

    constexpr int ASZ = 128 * 36;
    constexpr int BSZ = BNK ? 128 * 36 : 32 * 136;
    constexpr int STG = ASZ + BSZ;

    extern __shared__ float sm[];
    const uint32_t smU = (uint32_t)__cvta_generic_to_shared(sm);

    const int tid  = threadIdx.x;
    const int lane = tid & 31;
    const int wid  = tid >> 5;
    const int wm   = (wid >> 2) * 64;
    const int wn   = (wid & 3) * 32;
    const int gr   = lane >> 2;
    const int tg   = lane & 3;

    const int ar0 = tid >> 3;
    const int ac  = (tid & 7) * 4;
    const float* aPtr[4];
#pragma unroll
    for (int j = 0; j < 4; j++) {
        int r = mBase + ar0 + 32 * j;
        if (a_rows) r = a_rows[r < count ? r : count - 1];
        aPtr[j] = A + (long long)r * lda + ac;
    }
    const float* bPtr[4];
    int br0 = 0, bc = 0;
    if (BNK) {
#pragma unroll
        for (int j = 0; j < 4; j++)
            bPtr[j] = B + (long long)(nBase + ar0 + 32 * j) * ldb + ac;
    } else {
        br0 = tid >> 5;
        bc  = (tid & 31) * 4;
#pragma unroll
        for (int j = 0; j < 4; j++)
            bPtr[j] = B + (long long)(br0 + 8 * j) * ldb + nBase + bc;
    }

    const uint32_t aOff = (uint32_t)((ar0 * 36 + ac) * 4);
    const uint32_t bOff = BNK ? aOff : (uint32_t)((br0 * 136 + bc) * 4);

    auto issue_chunk = [&](int c, int buf) {
        const int k0 = c << 5;
        const uint32_t base = smU + (uint32_t)(buf * STG * 4);
#pragma unroll
        for (int j = 0; j < 4; j++)
            cpa16(base + aOff + (uint32_t)(j * 32 * 36 * 4), aPtr[j] + k0);
        const uint32_t bbase = base + (uint32_t)(ASZ * 4);
        if (BNK) {
#pragma unroll
            for (int j = 0; j < 4; j++)
                cpa16(bbase + bOff + (uint32_t)(j * 32 * 36 * 4), bPtr[j] + k0);
        } else {
#pragma unroll
            for (int j = 0; j < 4; j++)
                cpa16(bbase + bOff + (uint32_t)(j * 8 * 136 * 4), bPtr[j] + (long long)k0 * ldb);
        }
    };

    const int t8 = lane & 7;
    const uint32_t aFrag = smU +
        (uint32_t)(((wm + ((lane >> 3) & 1) * 8 + t8) * 36 + (lane >> 4) * 4) * 4);
    const uint32_t bFrag = smU + (uint32_t)(ASZ * 4) +
        (uint32_t)(((wn + (lane >> 4) * 8 + t8) * 36 + ((lane >> 3) & 1) * 4) * 4);

    float acc[4][4][4];
#pragma unroll
    for (int mi = 0; mi < 4; mi++)
#pragma unroll
        for (int ni = 0; ni < 4; ni++)
#pragma unroll
            for (int e = 0; e < 4; e++) acc[mi][ni][e] = 0.f;

    // 3-stage prologue: always commit two groups (second may be empty)
    issue_chunk(0, 0);
    CP_COMMIT();
    if (nCh > 1) issue_chunk(1, 1);
    CP_COMMIT();

    int buf = 0;
    for (int c = 0; c < nCh; c++) {
        CP_WAIT1();
        __syncthreads();

        const uint32_t bufB = (uint32_t)(buf * STG * 4);
        const float* Bs = sm + buf * STG + ASZ;

#pragma unroll
        for (int kk = 0; kk < 4; kk++) {
            const int ko = kk * 8;
            uint32_t af[4][4];
#pragma unroll
            for (int mi = 0; mi < 4; mi++)
                ldsm4(af[mi], aFrag + bufB + (uint32_t)((mi * 16 * 36 + ko) * 4));
            uint32_t bf[4][2];
            if (BNK) {
                uint32_t r4[4];
                ldsm4(r4, bFrag + bufB + (uint32_t)(ko * 4));
                bf[0][0] = r4[0]; bf[0][1] = r4[1]; bf[1][0] = r4[2]; bf[1][1] = r4[3];
                ldsm4(r4, bFrag + bufB + (uint32_t)((16 * 36 + ko) * 4));
                bf[2][0] = r4[0]; bf[2][1] = r4[1]; bf[3][0] = r4[2]; bf[3][1] = r4[3];
            } else {
#pragma unroll
                for (int ni = 0; ni < 4; ni++) {
                    const float* p = &Bs[(ko + tg) * 136 + wn + ni * 8 + gr];
                    bf[ni][0] = __float_as_uint(p[0]);
                    bf[ni][1] = __float_as_uint(p[4 * 136]);
                }
            }
#pragma unroll
            for (int mi = 0; mi < 4; mi++)
#pragma unroll
                for (int ni = 0; ni < 4; ni++)
                    mma_tf32(acc[mi][ni], af[mi], bf[ni]);
        }

        // issue chunk c+2 into the buffer read at iteration c-1 (safe: all warps passed the sync above)
        if (c + 2 < nCh) issue_chunk(c + 2, (buf + 2) % 3);
        CP_COMMIT();
        buf = (buf + 1) % 3;
    }

    // ---- epilogue ----
#pragma unroll
    for (int mi = 0; mi < 4; mi++) {
        const int gm0 = mBase + wm + mi * 16 + gr;
        const int gm1 = gm0 + 8;
        const bool ok0 = gm0 < count;
        const bool ok1 = gm1 < count;
#pragma unroll
        for (int ni = 0; ni < 4; ni++) {
            const int gn = nBase + wn + ni * 8 + tg * 2;
            float2 v0 = make_float2(acc[mi][ni][0], acc[mi][ni][1]);
            float2 v1 = make_float2(acc[mi][ni][2], acc[mi][ni][3]);
            if (bias) {
                float2 b = *(const float2*)(bias + gn);
                v0.x += b.x; v0.y += b.y; v1.x += b.x; v1.y += b.y;
            }
            if (roundOut) {
                v0.x = rnd_tf32(v0.x); v0.y = rnd_tf32(v0.y);
                v1.x = rnd_tf32(v1.x); v1.y = rnd_tf32(v1.y);
            }
            if (ok0) {
                if (residual) {
                    float2 r = *(const float2*)(residual + (long long)gm0 * ldr + gn);
                    v0.x += r.x; v0.y += r.y;
                }
                *(float2*)(C + (long long)gm0 * ldc + gn) = v0;
            }
            if (ok1) {
                if (residual) {
                    float2 r = *(const float2*)(residual + (long long)gm1 * ldr + gn);
                    v1.x += r.x; v1.y += r.y;
                }
                *(float2*)(C + (long long)gm1 * ldc + gn) = v1;
            }
        }
    }
}

// ---------------- elementwise / reduction kernels ----------------
__global__ void reset_cnt_kernel(int* cnt)
{
    if (threadIdx.x < Ed) cnt[threadIdx.x] = 0;
}

__global__ void rmsnorm_kernel(const float* __restrict__ x, const float* __restrict__ w,
                               float* __restrict__ y, float* __restrict__ y2)
{
    int s = blockIdx.x, tid = threadIdx.x;
    __shared__ float red[256];
    __shared__ float srs;
    const float* xr = x + (long long)s * Hd;
    float sum = 0.f;
    for (int h = tid; h < Hd; h += 256) { float v = xr[h]; sum += v * v; }
    red[tid] = sum; __syncthreads();
    for (int st = 128; st > 0; st >>= 1) {
        if (tid < st) red[tid] += red[tid + st];
        __syncthreads();
    }
    if (tid == 0) srs = rsqrtf(red[0] / (float)Hd + 1e-6f);
    __syncthreads();
    float rs = srs;
    float* yr = y + (long long)s * Hd;
    float* y2r = y2 ? y2 + (long long)s * Hd : nullptr;
    for (int h = tid; h < Hd; h += 256) {
        float v = w[h] * xr[h] * rs;
        yr[h] = rnd_tf32(v);
        if (y2r) y2r[h] = v;
    }
}

__global__ void rope_kernel(float* __restrict__ qkv)
{
    int i = blockIdx.x * 256 + threadIdx.x;
    int hi = i & 63;
    int h  = (i >> 6) & 15;
    int s  = i >> 10;
    float inv = powf(1000000.0f, -(float)hi / 64.0f);
    float ang = (float)s * inv;
    float sv, cv; sincosf(ang, &sv, &cv);
    long long base = (long long)s * QKVW + h * Dd + hi;
    float q1 = qkv[base], q2 = qkv[base + 64];
    qkv[base]      = rnd_tf32(q1 * cv - q2 * sv);
    qkv[base + 64] = rnd_tf32(q2 * cv + q1 * sv);
    float k1 = qkv[base + 2048], k2 = qkv[base + 2048 + 64];
    qkv[base + 2048]      = rnd_tf32(k1 * cv - k2 * sv);
    qkv[base + 2048 + 64] = rnd_tf32(k2 * cv + k1 * sv);
}

__global__ void softmax_kernel(float* __restrict__ scores)
{
    int s = blockIdx.x, h = blockIdx.y, tid = threadIdx.x;
    float* row = scores + ((long long)h * Sd + s) * Sd;
    const float scale = 0.08838834764831845f;
    int limit = ((s >> 7) + 1) << 7;
    float r[8];
    float mx = -3.4e38f;
#pragma unroll
    for (int t = 0; t < 8; t++) {
        int kk = t * 256 + tid;
        float v = -3.4e38f;
        if (kk <= s) v = row[kk] * scale;
        r[t] = v; mx = fmaxf(mx, v);
    }
    __shared__ float red[256];
    red[tid] = mx; __syncthreads();
    for (int st = 128; st > 0; st >>= 1) {
        if (tid < st) red[tid] = fmaxf(red[tid], red[tid + st]);
        __syncthreads();
    }
    mx = red[0]; __syncthreads();
    float sum = 0.f;
#pragma unroll
    for (int t = 0; t < 8; t++) {
        int kk = t * 256 + tid;
        if (kk <= s) { r[t] = expf(r[t] - mx); sum += r[t]; }
        else r[t] = 0.f;
    }
    red[tid] = sum; __syncthreads();
    for (int st = 128; st > 0; st >>= 1) {
        if (tid < st) red[tid] += red[tid + st];
        __syncthreads();
    }
    float inv = 1.0f / red[0];
#pragma unroll
    for (int t = 0; t < 8; t++) {
        int kk = t * 256 + tid;
        if (kk < limit) row[kk] = rnd_tf32(r[t] * inv);
    }
}

__global__ void router_kernel(const float* __restrict__ h2, const float* __restrict__ gate_w,
                              float* __restrict__ logits_out,
                              float* __restrict__ w4, int* __restrict__ sel4, int* __restrict__ pos4,
                              int* __restrict__ cnt, int* __restrict__ idx)
{
    int s = blockIdx.x, tid = threadIdx.x;
    __shared__ float red[256][8];
    float loc[8];
#pragma unroll
    for (int e = 0; e < 8; e++) loc[e] = 0.f;
    const float* hr = h2 + (long long)s * Hd;
    for (int h = tid; h < Hd; h += 256) {
        float hv = hr[h];
#pragma unroll
        for (int e = 0; e < 8; e++) loc[e] += hv * gate_w[h * 8 + e];
    }
#pragma unroll
    for (int e = 0; e < 8; e++) red[tid][e] = loc[e];
    __syncthreads();
    for (int st = 128; st > 0; st >>= 1) {
        if (tid < st) {
#pragma unroll
            for (int e = 0; e < 8; e++) red[tid][e] += red[tid + st][e];
        }
        __syncthreads();
    }
    if (tid == 0) {
        float l[8], p[8];
        float mx = -3.4e38f;
#pragma unroll
        for (int e = 0; e < 8; e++) { l[e] = red[0][e]; logits_out[s * 8 + e] = l[e]; mx = fmaxf(mx, l[e]); }
        float sum = 0.f;
#pragma unroll
        for (int e = 0; e < 8; e++) { p[e] = expf(l[e] - mx); sum += p[e]; }
#pragma unroll
        for (int e = 0; e < 8; e++) p[e] /= sum;
        bool used[8] = {false, false, false, false, false, false, false, false};
        for (int t = 0; t < 4; t++) {
            int best = -1; float bv = -1.f;
            for (int e = 0; e < 8; e++)
                if (!used[e] && p[e] > bv) { bv = p[e]; best = e; }
            used[best] = true;
            int pos = atomicAdd(&cnt[best], 1);
            idx[best * Sd + pos] = s;
            w4[s * 4 + t] = bv;
            sel4[s * 4 + t] = best;
            pos4[s * 4 + t] = pos;
        }
    }
}

// GU layout: [e][row][0..1407]=G, [1408..2815]=U
__global__ void silu_gu_kernel(float* __restrict__ GU, const int* __restrict__ cnt)
{
    long long i = (long long)blockIdx.x * 256 + threadIdx.x;   // 8*2048*1408
    int col = (int)(i % IEd);
    int row = (int)((i / IEd) & 2047);
    int e   = (int)(i / ((long long)Sd * IEd));
    if (row >= cnt[e]) return;
    long long base = ((long long)e * Sd + row) * GUW;
    float g = GU[base + col], u = GU[base + IEd + col];
    GU[base + col] = rnd_tf32((g / (1.f + expf(-g))) * u);
}

// SGU layout: [row][0..5631]=G, [5632..11263]=U ; writes G-half in place
__global__ void silu_sh_kernel(float* __restrict__ SGU)
{
    long long i = (long long)blockIdx.x * 256 + threadIdx.x;   // 2048*5632
    int col = (int)(i % ISd);
    int row = (int)(i / ISd);
    long long base = (long long)row * SGW;
    float g = SGU[base + col], u = SGU[base + ISd + col];
    SGU[base + col] = rnd_tf32((g / (1.f + expf(-g))) * u);
}

__global__ void sgate_kernel(const float* __restrict__ h2, const float* __restrict__ sgate,
                             float* __restrict__ sig)
{
    int s = blockIdx.x, tid = threadIdx.x;
    __shared__ float red[256];
    const float* hr = h2 + (long long)s * Hd;
    float sum = 0.f;
    for (int h = tid; h < Hd; h += 256) sum += hr[h] * sgate[h];
    red[tid] = sum; __syncthreads();
    for (int st = 128; st > 0; st >>= 1) {
        if (tid < st) red[tid] += red[tid + st];
        __syncthreads();
    }
    if (tid == 0) sig[s] = 1.f / (1.f + expf(-red[0]));
}

// out[s][c] += sum_t w4*Ye[sel][pos][c] + sig[s]*Ysh[s][c]   (fixed order -> deterministic)
__global__ void combine_kernel(float* __restrict__ out, const float* __restrict__ Ye,
                               const float* __restrict__ Ysh,
                               const float* __restrict__ w4, const int* __restrict__ sel4,
                               const int* __restrict__ pos4, const float* __restrict__ sig)
{
    int i = blockIdx.x * 256 + threadIdx.x;
    int s = i >> 11, c = i & 2047;
    float acc = out[i];
#pragma unroll
    for (int t = 0; t < 4; t++) {
        int e = sel4[s * 4 + t];
        int p = pos4[s * 4 + t];
        acc += w4[s * 4 + t] * Ye[((long long)e * Sd + p) * Hd + c];
    }
    out[i] = acc + sig[s] * Ysh[i];
}

// ---------------- host-side GEMM dispatch ----------------
static const int SMEM_T = 3 * (128 * 36 + 128 * 36) * 4;   // 110592 (BNK=true)
static const int SMEM_F = 3 * (128 * 36 + 32 * 136) * 4;   // 107520 (BNK=false)

static inline void tgemm(bool bnk, const float* A, const float* B, float* C,
                         int M, int N, int K, int lda, int ldb, int ldc,
                         long long sA = 0, long long sB = 0, long long sC = 0, int nz = 1,
                         const float* bias = nullptr,
                         const float* residual = nullptr, int ldr = 0,
                         const int* arows = nullptr, const int* acnt = nullptr,
                         int causal = 0, int roundOut = 0, int perZ = 0)
{
    dim3 grid(N / 128, (M + 127) / 128, nz);
    if (bnk)
        mgemm_kernel<true><<<grid, 256, SMEM_T>>>(A, B, C, M, N, K, lda, ldb, ldc,
                                                  sA, sB, sC, bias, residual, ldr, arows, acnt,
                                                  causal, roundOut, perZ);
    else
        mgemm_kernel<false><<<grid, 256, SMEM_F>>>(A, B, C, M, N, K, lda, ldb, ldc,
                                                   sA, sB, sC, bias, residual, ldr, arows, acnt,
                                                   causal, roundOut, perZ);
}

static inline void trT(const float* src, float* dst, int R, int C, int nz, long long dstZ)
{
    dim3 grid(C / 32, R / 32, nz);
    trT_kernel<<<grid, dim3(32, 8)>>>(src, dst, R, C, dstZ);
}

extern "C" void kernel_launch(void* const* d_in, const int* in_sizes, int n_in,
                              void* d_out, int out_size)
{
    cudaFuncSetAttribute(mgemm_kernel<true>,  cudaFuncAttributeMaxDynamicSharedMemorySize, SMEM_T);
    cudaFuncSetAttribute(mgemm_kernel<false>, cudaFuncAttributeMaxDynamicSharedMemorySize, SMEM_F);

    const float* x     = (const float*)d_in[0];
    const float* ln1   = (const float*)d_in[1];
    const float* ln2   = (const float*)d_in[2];
    const float* wq    = (const float*)d_in[3];
    const float* bq    = (const float*)d_in[4];
    const float* wk    = (const float*)d_in[5];
    const float* bk    = (const float*)d_in[6];
    const float* wv    = (const float*)d_in[7];
    const float* bv    = (const float*)d_in[8];
    const float* wo    = (const float*)d_in[9];
    const float* gate  = (const float*)d_in[10];
    const float* eg    = (const float*)d_in[11];
    const float* eu    = (const float*)d_in[12];
    const float* ed    = (const float*)d_in[13];
    const float* sg    = (const float*)d_in[14];
    const float* su    = (const float*)d_in[15];
    const float* sd    = (const float*)d_in[16];
    const float* sgate = (const float*)d_in[17];

    float* out        = (float*)d_out;
    float* out_x      = out;
    float* out_logits = out + (long long)Sd * Hd;

    float *h1, *qkv, *scores, *attn, *h2, *h2x, *GU, *Ye, *SGU, *Ysh, *sig, *w4, *bqkv;
    float *qkvT, *woT, *guT, *edT, *sguT, *sdT;
    int *cnt, *idx, *sel4, *pos4;
    cudaGetSymbolAddress((void**)&h1,     g_h1);
    cudaGetSymbolAddress((void**)&qkv,    g_qkv);
    cudaGetSymbolAddress((void**)&scores, g_scores);
    cudaGetSymbolAddress((void**)&attn,   g_attn);
    cudaGetSymbolAddress((void**)&h2,     g_h2);
    cudaGetSymbolAddress((void**)&h2x,    g_h2x);
    cudaGetSymbolAddress((void**)&GU,     g_GU);
    cudaGetSymbolAddress((void**)&Ye,     g_Ye);
    cudaGetSymbolAddress((void**)&SGU,    g_SGU);
    cudaGetSymbolAddress((void**)&Ysh,    g_Ysh);
    cudaGetSymbolAddress((void**)&sig,    g_sig);
    cudaGetSymbolAddress((void**)&w4,     g_w4);
    cudaGetSymbolAddress((void**)&bqkv,   g_bqkv);
    cudaGetSymbolAddress((void**)&cnt,    g_cnt);
    cudaGetSymbolAddress((void**)&idx,    g_idx);
    cudaGetSymbolAddress((void**)&sel4,   g_sel4);
    cudaGetSymbolAddress((void**)&pos4,   g_pos4);
    cudaGetSymbolAddress((void**)&qkvT,   g_qkvT);
    cudaGetSymbolAddress((void**)&woT,    g_woT);
    cudaGetSymbolAddress((void**)&guT,    g_guT);
    cudaGetSymbolAddress((void**)&edT,    g_edT);
    cudaGetSymbolAddress((void**)&sguT,   g_sguT);
    cudaGetSymbolAddress((void**)&sdT,    g_sdT);

    // 0. weight transposes (+tf32 rounding), fused layouts
    trT(wq, qkvT,                         Hd, Hd, 1, 0);
    trT(wk, qkvT + (long long)Hd * Hd,     Hd, Hd, 1, 0);
    trT(wv, qkvT + (long long)2 * Hd * Hd, Hd, Hd, 1, 0);
    trT(wo, woT, Hd, Hd, 1, 0);
    trT(eg, guT,                           Hd, IEd, Ed, (long long)GUW * Hd);
    trT(eu, guT + (long long)IEd * Hd,     Hd, IEd, Ed, (long long)GUW * Hd);
    trT(ed, edT, IEd, Hd, Ed, (long long)Hd * IEd);
    trT(sg, sguT,                          Hd, ISd, 1, 0);
    trT(su, sguT + (long long)ISd * Hd,    Hd, ISd, 1, 0);
    trT(sd, sdT, ISd, Hd, 1, 0);
    bias_cat_kernel<<<QKVW / 256, 256>>>(bq, bk, bv, bqkv);
    reset_cnt_kernel<<<1, 32>>>(cnt);

    // 1. rmsnorm -> h1
    rmsnorm_kernel<<<Sd, 256>>>(x, ln1, h1, nullptr);

    // 2. fused QKV projection (+bias, rounded)
    tgemm(true, h1, qkvT, qkv, Sd, QKVW, Hd, Hd, Hd, QKVW, 0, 0, 0, 1, bqkv,
          nullptr, 0, nullptr, nullptr, 0, 1);

    // 3. RoPE
    rope_kernel<<<(Sd * NHd * 64) / 256, 256>>>(qkv);

    // 4. scores = q @ k^T (per head, causal block-skip)
    tgemm(true, qkv, qkv + 2048, scores, Sd, Sd, Dd, QKVW, QKVW, Sd,
          128, 128, (long long)Sd * Sd, NHd, nullptr, nullptr, 0, nullptr, nullptr, 1);

    // 5. causal softmax
    softmax_kernel<<<dim3(Sd, NHd), 256>>>(scores);

    // 6. attn = probs @ v (K causally capped, rounded)
    tgemm(false, scores, qkv + 4096, attn, Sd, Dd, Sd, Sd, QKVW, Hd,
          (long long)Sd * Sd, 128, 128, NHd, nullptr, nullptr, 0, nullptr, nullptr, 2, 1);

    // 7. x2 = x + attn @ wo
    tgemm(true, attn, woT, out_x, Sd, Hd, Hd, Hd, Hd, Hd, 0, 0, 0, 1, nullptr, x, Hd);

    // 8. rmsnorm -> h2 (+ exact h2x)
    rmsnorm_kernel<<<Sd, 256>>>(out_x, ln2, h2, h2x);

    // 9. router
    router_kernel<<<Sd, 256>>>(h2x, gate, out_logits, w4, sel4, pos4, cnt, idx);

    // 10. routed MoE — batched across experts (z=8), fused G|U
    tgemm(true, h2, guT, GU, Sd, GUW, Hd, Hd, Hd, GUW,
          0, (long long)GUW * Hd, (long long)Sd * GUW, Ed,
          nullptr, nullptr, 0, idx, cnt, 0, 0, 1);
    silu_gu_kernel<<<(int)(((long long)Ed * Sd * IEd) / 256), 256>>>(GU, cnt);
    tgemm(true, GU, edT, Ye, Sd, Hd, IEd, GUW, IEd, Hd,
          (long long)Sd * GUW, (long long)Hd * IEd, (long long)Sd * Hd, Ed,
          nullptr, nullptr, 0, nullptr, cnt, 0, 0, 1);

    // 11. shared expert — fused sg|su
    tgemm(true, h2, sguT, SGU, Sd, SGW, Hd, Hd, Hd, SGW);
    silu_sh_kernel<<<(int)(((long long)Sd * ISd) / 256), 256>>>(SGU);
    tgemm(true, SGU, sdT, Ysh, Sd, Hd, ISd, SGW, ISd, Hd);
    sgate_kernel<<<Sd, 256>>>(h2x, sgate, sig);

    // 12. deterministic fused combine (MoE + shared)
    combine_kernel<<<(Sd * Hd) / 256, 256>>>(out_x, Ye, Ysh, w4, sel4, pos4, sig);

    (void)in_sizes; (void)n_in; (void)out_size;
}